// round 8
// baseline (speedup 1.0000x reference)
#include <cuda_runtime.h>
#include <cuda_bf16.h>
#include <cstdint>

// Problem constants
#define BB 64
#define PP 196
#define EE 2048
#define LL 32
#define VV 10000
#define EMB 512
#define DEC 512
#define ATT 512
#define TT 31   // L-1 steps

// ---------------- device scratch ----------------
__device__ __align__(16) int   d_sort_src[BB];
__device__ __align__(16) int   d_nb[TT + 1];
__device__ int   d_total;
__device__ __align__(16) int   d_rowmap[BB * TT];
__device__ __align__(16) float d_mean[BB * EE];
__device__ __align__(16) float d_h[BB * DEC];
__device__ __align__(16) float d_c[BB * DEC];
__device__ __align__(16) float d_hhist[(size_t)TT * BB * DEC];
__device__ __align__(16) float d_att1[(size_t)BB * PP * ATT];
__device__ __align__(16) float d_att2[BB * ATT];
__device__ __align__(16) float d_gate[BB * EE];
__device__ __align__(16) float d_awe[BB * EE];
__device__ __align__(16) float d_hg[BB * 2048];
__device__ __align__(16) float d_embc[(size_t)TT * BB * 2048];  // 16 MB
__device__ __align__(16) float d_part[8 * BB * 2048];

#define BUF_MEAN 0
#define BUF_H    1
#define BUF_C    2
#define BUF_AWE  5

__device__ __forceinline__ float* selbuf(int s) {
    switch (s) {
        case BUF_MEAN: return d_mean;
        case BUF_H:    return d_h;
        case BUF_C:    return d_c;
        case BUF_AWE:  return d_awe;
        default:       return nullptr;
    }
}

// ---------------- tf32 helpers ----------------
__device__ __forceinline__ float tf32r(float f) {
    uint32_t u;
    asm("cvt.rna.tf32.f32 %0, %1;" : "=r"(u) : "f"(f));
    return __uint_as_float(u);
}
__device__ __forceinline__ void mma_tf32(float* c, const uint32_t* a, const uint32_t* b) {
    asm volatile("mma.sync.aligned.m16n8k8.row.col.f32.tf32.tf32.f32 "
        "{%0,%1,%2,%3}, {%4,%5,%6,%7}, {%8,%9}, {%0,%1,%2,%3};"
        : "+f"(c[0]), "+f"(c[1]), "+f"(c[2]), "+f"(c[3])
        : "r"(a[0]), "r"(a[1]), "r"(a[2]), "r"(a[3]), "r"(b[0]), "r"(b[1]));
}

// ---------------- setup: argsort, nb counts, compact row map ----------------
__global__ void k_setup(const int* __restrict__ cap_len) {
    __shared__ int lens[BB];
    __shared__ int nbs[TT + 1];
    __shared__ int off[TT + 1];
    int b = threadIdx.x;
    if (b < BB) lens[b] = cap_len[b];
    __syncthreads();
    if (b < BB) {
        int rank = 0;
        int lb = lens[b];
        for (int j = 0; j < BB; j++) {
            int lj = lens[j];
            if (lj > lb || (lj == lb && j < b)) rank++;
        }
        d_sort_src[rank] = b;
    }
    if (b <= TT) {
        int cnt = 0;
        for (int j = 0; j < BB; j++) if (lens[j] - 1 > b) cnt++;
        d_nb[b] = cnt;
        nbs[b] = cnt;
    }
    __syncthreads();
    if (b == 0) {
        int a = 0;
        for (int t = 0; t < TT; t++) { off[t] = a; a += nbs[t]; }
        d_total = a;
    }
    __syncthreads();
    if (b < BB) {
        for (int t = 0; t < TT; t++)
            if (b < nbs[t]) d_rowmap[off[t] + b] = (t << 6) | b;
    }
}

__global__ void k_zero(float* __restrict__ out, size_t n) {
    size_t i = (size_t)blockIdx.x * blockDim.x + threadIdx.x;
    size_t stride = (size_t)gridDim.x * blockDim.x;
    for (; i < n; i += stride) out[i] = 0.0f;
}

__global__ void k_mean(const float* __restrict__ enc) {
    int b = blockIdx.y;
    int e = blockIdx.x * 256 + threadIdx.x;
    const float* base = enc + (size_t)d_sort_src[b] * PP * EE + e;
    float s = 0.0f;
    #pragma unroll 7
    for (int p = 0; p < PP; p++) s += base[(size_t)p * EE];
    d_mean[b * EE + e] = s * (1.0f / 196.0f);
}

// ---------------- split-K GEMM into d_part ----------------
__global__ void k_gemm(int xsel,
                       const float* __restrict__ W1,
                       int K, int N, int t, int S) {
    __shared__ __align__(16) float Xs[2][16][68];
    __shared__ __align__(16) float Ws[2][16][34];

    const float* X = selbuf(xsel);
    int tid = threadIdx.x;
    int nb = (t >= 0) ? d_nb[t] : BB;
    int n0 = blockIdx.x * 32;

    int s = blockIdx.y;
    int kbeg = s * (K / S);
    int ntiles = (K / S) / 16;

    int nl = tid & 15;
    int mg = tid >> 4;
    int m0 = mg << 2;
    bool rowact = (m0 < nb);

    int lm = tid >> 2, lk = (tid & 3) << 2;
    int wk = tid >> 4, wn = tid & 15;
    const float* Xrow = X + (size_t)lm * K;

    float acc[4][2];
    #pragma unroll
    for (int i = 0; i < 4; i++) { acc[i][0] = 0.f; acc[i][1] = 0.f; }

    float4 xr; float wr0, wr1;
    {
        int k0 = kbeg;
        xr = *reinterpret_cast<const float4*>(Xrow + k0 + lk);
        int kg = k0 + wk;
        wr0 = W1[(size_t)kg * N + n0 + wn];
        wr1 = W1[(size_t)kg * N + n0 + wn + 16];
    }
    Xs[0][lk + 0][lm] = xr.x; Xs[0][lk + 1][lm] = xr.y;
    Xs[0][lk + 2][lm] = xr.z; Xs[0][lk + 3][lm] = xr.w;
    Ws[0][wk][wn] = wr0; Ws[0][wk][wn + 16] = wr1;
    __syncthreads();

    for (int it = 0; it < ntiles; it++) {
        int cur = it & 1;
        bool more = (it + 1 < ntiles);
        if (more) {
            int k0 = kbeg + (it + 1) * 16;
            xr = *reinterpret_cast<const float4*>(Xrow + k0 + lk);
            int kg = k0 + wk;
            wr0 = W1[(size_t)kg * N + n0 + wn];
            wr1 = W1[(size_t)kg * N + n0 + wn + 16];
        }
        if (rowact) {
            #pragma unroll
            for (int kk = 0; kk < 16; kk++) {
                float4 xv = *reinterpret_cast<const float4*>(&Xs[cur][kk][m0]);
                float2 wv = *reinterpret_cast<const float2*>(&Ws[cur][kk][nl * 2]);
                acc[0][0] += xv.x * wv.x; acc[0][1] += xv.x * wv.y;
                acc[1][0] += xv.y * wv.x; acc[1][1] += xv.y * wv.y;
                acc[2][0] += xv.z * wv.x; acc[2][1] += xv.z * wv.y;
                acc[3][0] += xv.w * wv.x; acc[3][1] += xv.w * wv.y;
            }
        }
        if (more) {
            int nxt = cur ^ 1;
            Xs[nxt][lk + 0][lm] = xr.x; Xs[nxt][lk + 1][lm] = xr.y;
            Xs[nxt][lk + 2][lm] = xr.z; Xs[nxt][lk + 3][lm] = xr.w;
            Ws[nxt][wk][wn] = wr0; Ws[nxt][wk][wn + 16] = wr1;
        }
        __syncthreads();
    }

    if (!rowact) return;
    int na = n0 + nl * 2;
    #pragma unroll
    for (int j = 0; j < 4; j++) {
        int m = m0 + j;
        if (m < nb) {
            size_t base = ((size_t)(s * BB + m)) * N + na;
            d_part[base] = acc[j][0];
            d_part[base + 1] = acc[j][1];
        }
    }
}

__global__ void k_reduce(int N, int S, const float* __restrict__ b1, int ysel) {
    int idx = blockIdx.x * 256 + threadIdx.x;
    if (idx >= BB * N) return;
    int m = idx / N, n = idx - m * N;
    float v = b1 ? b1[n] : 0.f;
    for (int s = 0; s < S; s++) v += d_part[((size_t)(s * BB + m)) * N + n];
    selbuf(ysel)[(size_t)m * N + n] = v;
}

// ---------------- reduce: g = embc + hg + part0 + part1 + biases, then LSTM ----------------
__global__ void k_reduce_lstm(const float* __restrict__ bih, const float* __restrict__ bhh, int t) {
    int idx = blockIdx.x * 256 + threadIdx.x;
    int b = idx >> 9, d = idx & 511;
    if (b >= d_nb[t]) return;
    const float* e  = d_embc + ((size_t)((t << 6) | b)) * 2048;
    const float* hg = d_hg + (size_t)b * 2048;
    float gi = bih[d]        + bhh[d]        + e[d]        + hg[d];
    float gf = bih[512 + d]  + bhh[512 + d]  + e[512 + d]  + hg[512 + d];
    float gg = bih[1024 + d] + bhh[1024 + d] + e[1024 + d] + hg[1024 + d];
    float go = bih[1536 + d] + bhh[1536 + d] + e[1536 + d] + hg[1536 + d];
    #pragma unroll
    for (int s = 0; s < 2; s++) {
        const float* p = d_part + ((size_t)(s * BB + b)) * 2048;
        gi += p[d]; gf += p[512 + d]; gg += p[1024 + d]; go += p[1536 + d];
    }
    float c = d_c[b * DEC + d];
    float si = 1.0f / (1.0f + __expf(-gi));
    float sf = 1.0f / (1.0f + __expf(-gf));
    float so = 1.0f / (1.0f + __expf(-go));
    float cn = sf * c + si * tanhf(gg);
    float hn = so * tanhf(cn);
    d_c[b * DEC + d] = cn;
    d_h[b * DEC + d] = hn;
    d_hhist[((size_t)t * BB + b) * DEC + d] = hn;
}

// ---------------- fused att2 + gate + hg (h@Whh): X = d_h, K = 512 ----------------
// blocks 0..15: att2 ; 16..79: gate (sigmoid) ; 80..143: hg = h@Whh (raw)
__global__ void __launch_bounds__(256, 2) k_ag(
        const float* __restrict__ Wd, const float* __restrict__ bd,
        const float* __restrict__ Wb, const float* __restrict__ bb,
        const float* __restrict__ Whh, int t) {
    __shared__ __align__(16) float Xs[2][16][68];
    __shared__ __align__(16) float Ws[2][16][34];

    int bx = blockIdx.x;
    const float* W; const float* bias = nullptr; float* Y;
    int Nw, act, n0;
    int nb = d_nb[t];
    if (bx < 16)      { W = Wd;  bias = bd; Y = d_att2; Nw = ATT; act = 0; n0 = bx * 32; }
    else if (bx < 80) { W = Wb;  bias = bb; Y = d_gate; Nw = EE;  act = 1; n0 = (bx - 16) * 32; }
    else              { W = Whh;            Y = d_hg;   Nw = 2048; act = 2; n0 = (bx - 80) * 32; }

    int tid = threadIdx.x;
    int nl = tid & 15;
    int mg = tid >> 4;
    int m0 = mg << 2;
    bool rowact = (m0 < nb);

    int lm = tid >> 2, lk = (tid & 3) << 2;
    int wk = tid >> 4, wn = tid & 15;
    const float* Xrow = d_h + (size_t)lm * DEC;

    float acc[4][2];
    #pragma unroll
    for (int i = 0; i < 4; i++) { acc[i][0] = 0.f; acc[i][1] = 0.f; }

    float4 xr; float wr0, wr1;
    xr = *reinterpret_cast<const float4*>(Xrow + lk);
    wr0 = W[(size_t)wk * Nw + n0 + wn];
    wr1 = W[(size_t)wk * Nw + n0 + wn + 16];
    Xs[0][lk + 0][lm] = xr.x; Xs[0][lk + 1][lm] = xr.y;
    Xs[0][lk + 2][lm] = xr.z; Xs[0][lk + 3][lm] = xr.w;
    Ws[0][wk][wn] = wr0; Ws[0][wk][wn + 16] = wr1;
    __syncthreads();

    const int ntiles = DEC / 16;  // 32
    for (int it = 0; it < ntiles; it++) {
        int cur = it & 1;
        bool more = (it + 1 < ntiles);
        if (more) {
            int k0 = (it + 1) * 16;
            xr = *reinterpret_cast<const float4*>(Xrow + k0 + lk);
            int kg = k0 + wk;
            wr0 = W[(size_t)kg * Nw + n0 + wn];
            wr1 = W[(size_t)kg * Nw + n0 + wn + 16];
        }
        if (rowact) {
            #pragma unroll
            for (int kk = 0; kk < 16; kk++) {
                float4 xv = *reinterpret_cast<const float4*>(&Xs[cur][kk][m0]);
                float2 wv = *reinterpret_cast<const float2*>(&Ws[cur][kk][nl * 2]);
                acc[0][0] += xv.x * wv.x; acc[0][1] += xv.x * wv.y;
                acc[1][0] += xv.y * wv.x; acc[1][1] += xv.y * wv.y;
                acc[2][0] += xv.z * wv.x; acc[2][1] += xv.z * wv.y;
                acc[3][0] += xv.w * wv.x; acc[3][1] += xv.w * wv.y;
            }
        }
        if (more) {
            int nxt = cur ^ 1;
            Xs[nxt][lk + 0][lm] = xr.x; Xs[nxt][lk + 1][lm] = xr.y;
            Xs[nxt][lk + 2][lm] = xr.z; Xs[nxt][lk + 3][lm] = xr.w;
            Ws[nxt][wk][wn] = wr0; Ws[nxt][wk][wn + 16] = wr1;
        }
        __syncthreads();
    }

    if (!rowact) return;
    int na = n0 + nl * 2;
    float b0v = bias ? bias[na] : 0.f;
    float b1v = bias ? bias[na + 1] : 0.f;
    #pragma unroll
    for (int j = 0; j < 4; j++) {
        int m = m0 + j;
        if (m < nb) {
            float v0 = acc[j][0] + b0v;
            float v1 = acc[j][1] + b1v;
            if (act == 1) {
                v0 = 1.0f / (1.0f + __expf(-v0));
                v1 = 1.0f / (1.0f + __expf(-v1));
            }
            Y[(size_t)m * Nw + na] = v0;
            Y[(size_t)m * Nw + na + 1] = v1;
        }
    }
}

// ---------------- att1 = enc[sorted] @ We + be : tf32 MMA, 128x64 tile ----------------
__global__ void __launch_bounds__(256, 2) k_att1_mma(const float* __restrict__ enc,
                                                     const float* __restrict__ We,
                                                     const float* __restrict__ be) {
    __shared__ float As[2][16][136];
    __shared__ float Bs[2][16][72];
    int tid = threadIdx.x;
    int warp = tid >> 5, lane = tid & 31;
    int g = lane >> 2, tk = lane & 3;
    int mw = (warp & 3) * 32, nw = (warp >> 2) * 32;
    int rowBase = blockIdx.x * 128, colBase = blockIdx.y * 64;

    int lm = tid >> 1, lk = (tid & 1) << 3;
    int r = rowBase + lm;
    int bidx = r / PP, pidx = r % PP;
    const float* Arow = enc + ((size_t)d_sort_src[bidx] * PP + pidx) * EE;
    int bk = tid >> 4, bn = (tid & 15) << 2;

    float acc[2][4][4];
    #pragma unroll
    for (int i = 0; i < 2; i++)
        #pragma unroll
        for (int j = 0; j < 4; j++)
            #pragma unroll
            for (int q = 0; q < 4; q++) acc[i][j][q] = 0.f;

    float4 av0, av1, bv;
    av0 = *reinterpret_cast<const float4*>(Arow + lk);
    av1 = *reinterpret_cast<const float4*>(Arow + lk + 4);
    bv  = *reinterpret_cast<const float4*>(We + (size_t)bk * ATT + colBase + bn);
    As[0][lk + 0][lm] = tf32r(av0.x); As[0][lk + 1][lm] = tf32r(av0.y);
    As[0][lk + 2][lm] = tf32r(av0.z); As[0][lk + 3][lm] = tf32r(av0.w);
    As[0][lk + 4][lm] = tf32r(av1.x); As[0][lk + 5][lm] = tf32r(av1.y);
    As[0][lk + 6][lm] = tf32r(av1.z); As[0][lk + 7][lm] = tf32r(av1.w);
    *reinterpret_cast<float4*>(&Bs[0][bk][bn]) =
        make_float4(tf32r(bv.x), tf32r(bv.y), tf32r(bv.z), tf32r(bv.w));
    __syncthreads();

    const int ntiles = EE / 16;  // 128
    for (int it = 0; it < ntiles; it++) {
        int cur = it & 1;
        bool more = (it + 1 < ntiles);
        if (more) {
            int k0 = (it + 1) * 16;
            av0 = *reinterpret_cast<const float4*>(Arow + k0 + lk);
            av1 = *reinterpret_cast<const float4*>(Arow + k0 + lk + 4);
            bv  = *reinterpret_cast<const float4*>(We + (size_t)(k0 + bk) * ATT + colBase + bn);
        }
        #pragma unroll
        for (int ks = 0; ks < 16; ks += 8) {
            uint32_t a[2][4], bfr[4][2];
            #pragma unroll
            for (int i = 0; i < 2; i++) {
                a[i][0] = __float_as_uint(As[cur][ks + tk][mw + i * 16 + g]);
                a[i][1] = __float_as_uint(As[cur][ks + tk][mw + i * 16 + g + 8]);
                a[i][2] = __float_as_uint(As[cur][ks + tk + 4][mw + i * 16 + g]);
                a[i][3] = __float_as_uint(As[cur][ks + tk + 4][mw + i * 16 + g + 8]);
            }
            #pragma unroll
            for (int j = 0; j < 4; j++) {
                bfr[j][0] = __float_as_uint(Bs[cur][ks + tk][nw + j * 8 + g]);
                bfr[j][1] = __float_as_uint(Bs[cur][ks + tk + 4][nw + j * 8 + g]);
            }
            #pragma unroll
            for (int i = 0; i < 2; i++)
                #pragma unroll
                for (int j = 0; j < 4; j++)
                    mma_tf32(acc[i][j], a[i], bfr[j]);
        }
        if (more) {
            int nxt = cur ^ 1;
            As[nxt][lk + 0][lm] = tf32r(av0.x); As[nxt][lk + 1][lm] = tf32r(av0.y);
            As[nxt][lk + 2][lm] = tf32r(av0.z); As[nxt][lk + 3][lm] = tf32r(av0.w);
            As[nxt][lk + 4][lm] = tf32r(av1.x); As[nxt][lk + 5][lm] = tf32r(av1.y);
            As[nxt][lk + 6][lm] = tf32r(av1.z); As[nxt][lk + 7][lm] = tf32r(av1.w);
            *reinterpret_cast<float4*>(&Bs[nxt][bk][bn]) =
                make_float4(tf32r(bv.x), tf32r(bv.y), tf32r(bv.z), tf32r(bv.w));
        }
        __syncthreads();
    }

    #pragma unroll
    for (int i = 0; i < 2; i++) {
        int row0 = rowBase + mw + i * 16 + g;
        #pragma unroll
        for (int j = 0; j < 4; j++) {
            int col = colBase + nw + j * 8 + tk * 2;
            float be0 = be[col], be1 = be[col + 1];
            float2 o0 = make_float2(acc[i][j][0] + be0, acc[i][j][1] + be1);
            float2 o1 = make_float2(acc[i][j][2] + be0, acc[i][j][3] + be1);
            *reinterpret_cast<float2*>(d_att1 + (size_t)row0 * ATT + col) = o0;
            *reinterpret_cast<float2*>(d_att1 + (size_t)(row0 + 8) * ATT + col) = o1;
        }
    }
}

// ---------------- generic tf32 MMA over compact rows: A = gathered rows, K=512 ----------------
// mode 0: preds — A from d_hhist, bias add, scatter to out[b*TT+t]
// mode 1: embc  — A from emb[caps], no bias, write d_embc[mapped]
__global__ void __launch_bounds__(256, 2) k_rows_mma(const float* __restrict__ W,
                                                     const float* __restrict__ bias,
                                                     float* __restrict__ out,
                                                     const int* __restrict__ caps,
                                                     int Nw, int mode) {
    int total = d_total;
    int rowBase = blockIdx.x * 128;
    if (rowBase >= total) return;
    int colBase = blockIdx.y * 64;

    __shared__ float As[2][16][136];
    __shared__ float Bs[2][16][72];
    int tid = threadIdx.x;
    int warp = tid >> 5, lane = tid & 31;
    int g = lane >> 2, tk = lane & 3;
    int mw = (warp & 3) * 32, nw = (warp >> 2) * 32;

    int lm = tid >> 1, lk = (tid & 1) << 3;
    int r = rowBase + lm;
    bool rvalid = (r < total);
    const float* Arow;
    if (mode == 0) {
        Arow = d_hhist + (size_t)(rvalid ? d_rowmap[r] : 0) * DEC;
    } else {
        int mapped = rvalid ? d_rowmap[r] : 0;
        int t = mapped >> 6, b = mapped & 63;
        int cap = caps[d_sort_src[b] * LL + t];
        Arow = /*emb base*/ out == nullptr ? nullptr : nullptr;  // unused placeholder
        Arow = (const float*)caps;  // overwritten below
        Arow = d_hhist;             // placate compiler; real assignment next line
        Arow = nullptr;
        Arow = (const float*)0;
        Arow = (const float*)( (const char*)0 );
        // real: emb passed via bias? -> see k_embc wrapper below
        (void)cap;
    }
    // NOTE: embc path handled by dedicated kernel below; this kernel only does mode 0.
    int bk = tid >> 4, bn = (tid & 15) << 2;
    int bcol = colBase + bn;
    bool cvalid = (bcol < Nw);

    float acc[2][4][4];
    #pragma unroll
    for (int i = 0; i < 2; i++)
        #pragma unroll
        for (int j = 0; j < 4; j++)
            #pragma unroll
            for (int q = 0; q < 4; q++) acc[i][j][q] = 0.f;

    float4 av0, av1, bv;
    auto loadA = [&](int k0) {
        if (rvalid) {
            av0 = *reinterpret_cast<const float4*>(Arow + k0 + lk);
            av1 = *reinterpret_cast<const float4*>(Arow + k0 + lk + 4);
        } else {
            av0 = make_float4(0.f, 0.f, 0.f, 0.f);
            av1 = av0;
        }
    };
    auto loadB = [&](int k0) {
        if (cvalid) bv = *reinterpret_cast<const float4*>(W + (size_t)(k0 + bk) * Nw + bcol);
        else        bv = make_float4(0.f, 0.f, 0.f, 0.f);
    };

    loadA(0); loadB(0);
    As[0][lk + 0][lm] = tf32r(av0.x); As[0][lk + 1][lm] = tf32r(av0.y);
    As[0][lk + 2][lm] = tf32r(av0.z); As[0][lk + 3][lm] = tf32r(av0.w);
    As[0][lk + 4][lm] = tf32r(av1.x); As[0][lk + 5][lm] = tf32r(av1.y);
    As[0][lk + 6][lm] = tf32r(av1.z); As[0][lk + 7][lm] = tf32r(av1.w);
    *reinterpret_cast<float4*>(&Bs[0][bk][bn]) =
        make_float4(tf32r(bv.x), tf32r(bv.y), tf32r(bv.z), tf32r(bv.w));
    __syncthreads();

    const int ntiles = DEC / 16;
    for (int it = 0; it < ntiles; it++) {
        int cur = it & 1;
        bool more = (it + 1 < ntiles);
        if (more) { loadA((it + 1) * 16); loadB((it + 1) * 16); }
        #pragma unroll
        for (int ks = 0; ks < 16; ks += 8) {
            uint32_t a[2][4], bfr[4][2];
            #pragma unroll
            for (int i = 0; i < 2; i++) {
                a[i][0] = __float_as_uint(As[cur][ks + tk][mw + i * 16 + g]);
                a[i][1] = __float_as_uint(As[cur][ks + tk][mw + i * 16 + g + 8]);
                a[i][2] = __float_as_uint(As[cur][ks + tk + 4][mw + i * 16 + g]);
                a[i][3] = __float_as_uint(As[cur][ks + tk + 4][mw + i * 16 + g + 8]);
            }
            #pragma unroll
            for (int j = 0; j < 4; j++) {
                bfr[j][0] = __float_as_uint(Bs[cur][ks + tk][nw + j * 8 + g]);
                bfr[j][1] = __float_as_uint(Bs[cur][ks + tk + 4][nw + j * 8 + g]);
            }
            #pragma unroll
            for (int i = 0; i < 2; i++)
                #pragma unroll
                for (int j = 0; j < 4; j++)
                    mma_tf32(acc[i][j], a[i], bfr[j]);
        }
        if (more) {
            int nxt = cur ^ 1;
            As[nxt][lk + 0][lm] = tf32r(av0.x); As[nxt][lk + 1][lm] = tf32r(av0.y);
            As[nxt][lk + 2][lm] = tf32r(av0.z); As[nxt][lk + 3][lm] = tf32r(av0.w);
            As[nxt][lk + 4][lm] = tf32r(av1.x); As[nxt][lk + 5][lm] = tf32r(av1.y);
            As[nxt][lk + 6][lm] = tf32r(av1.z); As[nxt][lk + 7][lm] = tf32r(av1.w);
            *reinterpret_cast<float4*>(&Bs[nxt][bk][bn]) =
                make_float4(tf32r(bv.x), tf32r(bv.y), tf32r(bv.z), tf32r(bv.w));
        }
        __syncthreads();
    }

    #pragma unroll
    for (int i = 0; i < 2; i++) {
        #pragma unroll
        for (int j = 0; j < 4; j++) {
            int col = colBase + nw + j * 8 + tk * 2;
            if (col >= Nw) continue;
            float bf0 = bias[col], bf1 = bias[col + 1];
            #pragma unroll
            for (int h = 0; h < 2; h++) {
                int rr = rowBase + mw + i * 16 + g + h * 8;
                if (rr < total) {
                    int mapped = d_rowmap[rr];
                    int t = mapped >> 6, b = mapped & 63;
                    float* orow = out + ((size_t)b * TT + t) * VV;
                    orow[col]     = acc[i][j][h * 2]     + bf0;
                    orow[col + 1] = acc[i][j][h * 2 + 1] + bf1;
                }
            }
        }
    }
}

// ---------------- embc = embs(active rows) @ Wih[0:512] : tf32 MMA ----------------
__global__ void __launch_bounds__(256, 2) k_embc_mma(const float* __restrict__ emb,
                                                     const int* __restrict__ caps,
                                                     const float* __restrict__ Wih) {
    int total = d_total;
    int rowBase = blockIdx.x * 128;
    if (rowBase >= total) return;
    int colBase = blockIdx.y * 64;
    const int Nw = 2048;

    __shared__ float As[2][16][136];
    __shared__ float Bs[2][16][72];
    int tid = threadIdx.x;
    int warp = tid >> 5, lane = tid & 31;
    int g = lane >> 2, tk = lane & 3;
    int mw = (warp & 3) * 32, nw = (warp >> 2) * 32;

    int lm = tid >> 1, lk = (tid & 1) << 3;
    int r = rowBase + lm;
    bool rvalid = (r < total);
    const float* Arow;
    {
        int mapped = rvalid ? d_rowmap[r] : 0;
        int t = mapped >> 6, b = mapped & 63;
        int cap = caps[d_sort_src[b] * LL + t];
        Arow = emb + (size_t)cap * EMB;
    }
    int bk = tid >> 4, bn = (tid & 15) << 2;
    int bcol = colBase + bn;

    float acc[2][4][4];
    #pragma unroll
    for (int i = 0; i < 2; i++)
        #pragma unroll
        for (int j = 0; j < 4; j++)
            #pragma unroll
            for (int q = 0; q < 4; q++) acc[i][j][q] = 0.f;

    float4 av0, av1, bv;
    auto loadA = [&](int k0) {
        if (rvalid) {
            av0 = *reinterpret_cast<const float4*>(Arow + k0 + lk);
            av1 = *reinterpret_cast<const float4*>(Arow + k0 + lk + 4);
        } else {
            av0 = make_float4(0.f, 0.f, 0.f, 0.f);
            av1 = av0;
        }
    };
    auto loadB = [&](int k0) {
        bv = *reinterpret_cast<const float4*>(Wih + (size_t)(k0 + bk) * Nw + bcol);
    };

    loadA(0); loadB(0);
    As[0][lk + 0][lm] = tf32r(av0.x); As[0][lk + 1][lm] = tf32r(av0.y);
    As[0][lk + 2][lm] = tf32r(av0.z); As[0][lk + 3][lm] = tf32r(av0.w);
    As[0][lk + 4][lm] = tf32r(av1.x); As[0][lk + 5][lm] = tf32r(av1.y);
    As[0][lk + 6][lm] = tf32r(av1.z); As[0][lk + 7][lm] = tf32r(av1.w);
    *reinterpret_cast<float4*>(&Bs[0][bk][bn]) =
        make_float4(tf32r(bv.x), tf32r(bv.y), tf32r(bv.z), tf32r(bv.w));
    __syncthreads();

    const int ntiles = EMB / 16;  // 32
    for (int it = 0; it < ntiles; it++) {
        int cur = it & 1;
        bool more = (it + 1 < ntiles);
        if (more) { loadA((it + 1) * 16); loadB((it + 1) * 16); }
        #pragma unroll
        for (int ks = 0; ks < 16; ks += 8) {
            uint32_t a[2][4], bfr[4][2];
            #pragma unroll
            for (int i = 0; i < 2; i++) {
                a[i][0] = __float_as_uint(As[cur][ks + tk][mw + i * 16 + g]);
                a[i][1] = __float_as_uint(As[cur][ks + tk][mw + i * 16 + g + 8]);
                a[i][2] = __float_as_uint(As[cur][ks + tk + 4][mw + i * 16 + g]);
                a[i][3] = __float_as_uint(As[cur][ks + tk + 4][mw + i * 16 + g + 8]);
            }
            #pragma unroll
            for (int j = 0; j < 4; j++) {
                bfr[j][0] = __float_as_uint(Bs[cur][ks + tk][nw + j * 8 + g]);
                bfr[j][1] = __float_as_uint(Bs[cur][ks + tk + 4][nw + j * 8 + g]);
            }
            #pragma unroll
            for (int i = 0; i < 2; i++)
                #pragma unroll
                for (int j = 0; j < 4; j++)
                    mma_tf32(acc[i][j], a[i], bfr[j]);
        }
        if (more) {
            int nxt = cur ^ 1;
            As[nxt][lk + 0][lm] = tf32r(av0.x); As[nxt][lk + 1][lm] = tf32r(av0.y);
            As[nxt][lk + 2][lm] = tf32r(av0.z); As[nxt][lk + 3][lm] = tf32r(av0.w);
            As[nxt][lk + 4][lm] = tf32r(av1.x); As[nxt][lk + 5][lm] = tf32r(av1.y);
            As[nxt][lk + 6][lm] = tf32r(av1.z); As[nxt][lk + 7][lm] = tf32r(av1.w);
            *reinterpret_cast<float4*>(&Bs[nxt][bk][bn]) =
                make_float4(tf32r(bv.x), tf32r(bv.y), tf32r(bv.z), tf32r(bv.w));
        }
        __syncthreads();
    }

    #pragma unroll
    for (int i = 0; i < 2; i++) {
        #pragma unroll
        for (int j = 0; j < 4; j++) {
            int col = colBase + nw + j * 8 + tk * 2;
            #pragma unroll
            for (int h = 0; h < 2; h++) {
                int rr = rowBase + mw + i * 16 + g + h * 8;
                if (rr < total) {
                    int mapped = d_rowmap[rr];
                    float* orow = d_embc + (size_t)mapped * 2048;
                    orow[col]     = acc[i][j][h * 2];
                    orow[col + 1] = acc[i][j][h * 2 + 1];
                }
            }
        }
    }
}

// ---------------- fused: e -> softmax -> awe (512 threads, 1 block/b) ----------------
__global__ void __launch_bounds__(512, 2) k_attend(
        const float* __restrict__ enc,
        const float* __restrict__ Wf, const float* __restrict__ bf,
        float* __restrict__ out_alphas, int t) {
    int b = blockIdx.x;
    if (b >= d_nb[t]) return;
    __shared__ __align__(16) float a2[ATT];
    __shared__ __align__(16) float wf[ATT];
    __shared__ float es[PP];
    __shared__ float red[16];
    __shared__ float redsum[16];
    int tid = threadIdx.x;
    a2[tid] = d_att2[b * ATT + tid];
    wf[tid] = Wf[tid];
    __syncthreads();
    int lane = tid & 31, warp = tid >> 5;

    const float4* a24 = reinterpret_cast<const float4*>(a2);
    const float4* wf4 = reinterpret_cast<const float4*>(wf);
    for (int p = warp; p < PP; p += 16) {
        const float4* row4 = reinterpret_cast<const float4*>(d_att1 + ((size_t)b * PP + p) * ATT);
        float s = 0.f;
        #pragma unroll
        for (int i = 0; i < 4; i++) {
            int idx = lane + i * 32;
            float4 v = row4[idx];
            float4 a = a24[idx];
            float4 w = wf4[idx];
            s += fmaxf(v.x + a.x, 0.f) * w.x;
            s += fmaxf(v.y + a.y, 0.f) * w.y;
            s += fmaxf(v.z + a.z, 0.f) * w.z;
            s += fmaxf(v.w + a.w, 0.f) * w.w;
        }
        #pragma unroll
        for (int off = 16; off > 0; off >>= 1) s += __shfl_xor_sync(0xffffffffu, s, off);
        if (lane == 0) es[p] = s + bf[0];
    }
    __syncthreads();

    float v = (tid < PP) ? es[tid] : -1e30f;
    float m = v;
    #pragma unroll
    for (int off = 16; off > 0; off >>= 1) m = fmaxf(m, __shfl_xor_sync(0xffffffffu, m, off));
    if (lane == 0) red[warp] = m;
    __syncthreads();
    if (tid == 0) {
        float mm = red[0];
        for (int i = 1; i < 16; i++) mm = fmaxf(mm, red[i]);
        red[0] = mm;
    }
    __syncthreads();
    float smax = red[0];
    float ev = (tid < PP) ? __expf(v - smax) : 0.f;
    float s = ev;
    #pragma unroll
    for (int off = 16; off > 0; off >>= 1) s += __shfl_xor_sync(0xffffffffu, s, off);
    if (lane == 0) redsum[warp] = s;
    __syncthreads();
    if (tid == 0) {
        float ss = redsum[0];
        for (int i = 1; i < 16; i++) ss += redsum[i];
        redsum[0] = ss;
    }
    __syncthreads();
    float inv = 1.0f / redsum[0];
    float al = ev * inv;
    if (tid < PP) {
        es[tid] = al;
        out_alphas[((size_t)b * TT + t) * PP + tid] = al;
    }
    __syncthreads();

    int src = d_sort_src[b];
    const float4* enc4 = reinterpret_cast<const float4*>(enc + (size_t)src * PP * EE);
    float4 acc = make_float4(0.f, 0.f, 0.f, 0.f);
    #pragma unroll 4
    for (int p = 0; p < PP; p++) {
        float alp = es[p];
        float4 e4 = enc4[p * 512 + tid];
        acc.x += alp * e4.x; acc.y += alp * e4.y;
        acc.z += alp * e4.z; acc.w += alp * e4.w;
    }
    float4 g4 = reinterpret_cast<const float4*>(d_gate + (size_t)b * EE)[tid];
    reinterpret_cast<float4*>(d_awe + (size_t)b * EE)[tid] =
        make_float4(acc.x * g4.x, acc.y * g4.y, acc.z * g4.z, acc.w * g4.w);
}

// ---------------- host launch ----------------
extern "C" void kernel_launch(void* const* d_in, const int* in_sizes, int n_in,
                              void* d_out, int out_size) {
    const float* enc  = (const float*)d_in[0];
    const int*   caps = (const int*)d_in[1];
    const int*   clen = (const int*)d_in[2];
    const float* emb  = (const float*)d_in[3];
    const float* We   = (const float*)d_in[4];
    const float* be   = (const float*)d_in[5];
    const float* Wd   = (const float*)d_in[6];
    const float* bd   = (const float*)d_in[7];
    const float* Wf   = (const float*)d_in[8];
    const float* bf   = (const float*)d_in[9];
    const float* Wih  = (const float*)d_in[10];
    const float* bih  = (const float*)d_in[11];
    const float* Whh  = (const float*)d_in[12];
    const float* bhh  = (const float*)d_in[13];
    const float* Wb   = (const float*)d_in[14];
    const float* bb   = (const float*)d_in[15];
    const float* Whi  = (const float*)d_in[16];
    const float* bhi  = (const float*)d_in[17];
    const float* Wci  = (const float*)d_in[18];
    const float* bci  = (const float*)d_in[19];
    const float* Wfc  = (const float*)d_in[20];
    const float* bfc  = (const float*)d_in[21];
    float* out = (float*)d_out;
    float* out_alphas = out + (size_t)BB * TT * VV;

    k_setup<<<1, 64>>>(clen);
    k_zero<<<2048, 256>>>(out, (size_t)out_size);
    k_mean<<<dim3(8, BB), 256>>>(enc);

    // h0 / c0 (split-K 8 over K=2048)
    k_gemm<<<dim3(16, 8), 256>>>(BUF_MEAN, Whi, EE, DEC, -1, 8);
    k_reduce<<<128, 256>>>(DEC, 8, bhi, BUF_H);
    k_gemm<<<dim3(16, 8), 256>>>(BUF_MEAN, Wci, EE, DEC, -1, 8);
    k_reduce<<<128, 256>>>(DEC, 8, bci, BUF_C);

    // att1 via tf32 tensor cores
    k_att1_mma<<<dim3(98, 8), 256>>>(enc, We, be);

    // embc = embs(active rows) @ Wih[0:512] — off the per-step critical path
    k_embc_mma<<<dim3(16, 32), 256>>>(emb, caps, Wih);

    for (int t = 0; t < TT; t++) {
        // att2 + gate + hg(h@Whh) fused
        k_ag<<<144, 256>>>(Wd, bd, Wb, bb, Whh, t);
        // attention: e -> softmax -> awe (gated)
        k_attend<<<BB, 512>>>(enc, Wf, bf, out_alphas, t);
        // awe part: d_awe @ Wih[512:2560] (K=2048, split-K 2)
        k_gemm<<<dim3(64, 2), 256>>>(BUF_AWE, Wih + (size_t)512 * 2048, 2048, 2048, t, 2);
        // g = embc + hg + partials + biases, LSTM pointwise
        k_reduce_lstm<<<128, 256>>>(bih, bhh, t);
    }

    // batched vocab projection via tf32 tensor cores
    k_rows_mma<<<dim3(16, 157), 256>>>(Wfc, bfc, out, caps, VV, 0);
}

// round 9
// speedup vs baseline: 1.2600x; 1.2600x over previous
#include <cuda_runtime.h>
#include <cuda_bf16.h>
#include <cstdint>

// Problem constants
#define BB 64
#define PP 196
#define EE 2048
#define LL 32
#define VV 10000
#define EMB 512
#define DEC 512
#define ATT 512
#define TT 31   // L-1 steps

// ---------------- device scratch ----------------
__device__ __align__(16) int   d_sort_src[BB];
__device__ __align__(16) int   d_nb[TT + 1];
__device__ int   d_total;
__device__ __align__(16) int   d_rowmap[BB * TT];
__device__ __align__(16) float d_mean[BB * EE];
__device__ __align__(16) float d_h[BB * DEC];
__device__ __align__(16) float d_c[BB * DEC];
__device__ __align__(16) float d_hhist[(size_t)TT * BB * DEC];
__device__ __align__(16) float d_att1[(size_t)BB * PP * ATT];
__device__ __align__(16) float d_awe[BB * EE];
__device__ __align__(16) float d_embc[(size_t)TT * BB * 2048];  // 16 MB
__device__ __align__(16) float d_part[8 * BB * 2048];
// phase-A partials: [split(2)][b(64)][col(4608)] — cols: 0..511 att2, 512..2559 gate, 2560..4607 hg
#define AGC 4608
__device__ __align__(16) float d_agp[2 * BB * AGC];

#define BUF_MEAN 0
#define BUF_H    1
#define BUF_C    2
#define BUF_AWE  5

__device__ __forceinline__ float* selbuf(int s) {
    switch (s) {
        case BUF_MEAN: return d_mean;
        case BUF_H:    return d_h;
        case BUF_C:    return d_c;
        case BUF_AWE:  return d_awe;
        default:       return nullptr;
    }
}

// ---------------- tf32 helpers ----------------
__device__ __forceinline__ float tf32r(float f) {
    uint32_t u;
    asm("cvt.rna.tf32.f32 %0, %1;" : "=r"(u) : "f"(f));
    return __uint_as_float(u);
}
__device__ __forceinline__ void mma_tf32(float* c, const uint32_t* a, const uint32_t* b) {
    asm volatile("mma.sync.aligned.m16n8k8.row.col.f32.tf32.tf32.f32 "
        "{%0,%1,%2,%3}, {%4,%5,%6,%7}, {%8,%9}, {%0,%1,%2,%3};"
        : "+f"(c[0]), "+f"(c[1]), "+f"(c[2]), "+f"(c[3])
        : "r"(a[0]), "r"(a[1]), "r"(a[2]), "r"(a[3]), "r"(b[0]), "r"(b[1]));
}

// ---------------- setup ----------------
__global__ void k_setup(const int* __restrict__ cap_len) {
    __shared__ int lens[BB];
    __shared__ int nbs[TT + 1];
    __shared__ int off[TT + 1];
    int b = threadIdx.x;
    if (b < BB) lens[b] = cap_len[b];
    __syncthreads();
    if (b < BB) {
        int rank = 0;
        int lb = lens[b];
        for (int j = 0; j < BB; j++) {
            int lj = lens[j];
            if (lj > lb || (lj == lb && j < b)) rank++;
        }
        d_sort_src[rank] = b;
    }
    if (b <= TT) {
        int cnt = 0;
        for (int j = 0; j < BB; j++) if (lens[j] - 1 > b) cnt++;
        d_nb[b] = cnt;
        nbs[b] = cnt;
    }
    __syncthreads();
    if (b == 0) {
        int a = 0;
        for (int t = 0; t < TT; t++) { off[t] = a; a += nbs[t]; }
        d_total = a;
    }
    __syncthreads();
    if (b < BB) {
        for (int t = 0; t < TT; t++)
            if (b < nbs[t]) d_rowmap[off[t] + b] = (t << 6) | b;
    }
}

__global__ void k_zero(float* __restrict__ out, size_t n) {
    size_t i = (size_t)blockIdx.x * blockDim.x + threadIdx.x;
    size_t stride = (size_t)gridDim.x * blockDim.x;
    for (; i < n; i += stride) out[i] = 0.0f;
}

__global__ void k_mean(const float* __restrict__ enc) {
    int b = blockIdx.y;
    int e = blockIdx.x * 256 + threadIdx.x;
    const float* base = enc + (size_t)d_sort_src[b] * PP * EE + e;
    float s = 0.0f;
    #pragma unroll 7
    for (int p = 0; p < PP; p++) s += base[(size_t)p * EE];
    d_mean[b * EE + e] = s * (1.0f / 196.0f);
}

// ---------------- split-K GEMM into d_part ----------------
__global__ void k_gemm(int xsel,
                       const float* __restrict__ W1,
                       int K, int N, int t, int S) {
    __shared__ __align__(16) float Xs[2][16][68];
    __shared__ __align__(16) float Ws[2][16][34];

    const float* X = selbuf(xsel);
    int tid = threadIdx.x;
    int nb = (t >= 0) ? d_nb[t] : BB;
    int n0 = blockIdx.x * 32;

    int s = blockIdx.y;
    int kbeg = s * (K / S);
    int ntiles = (K / S) / 16;

    int nl = tid & 15;
    int mg = tid >> 4;
    int m0 = mg << 2;
    bool rowact = (m0 < nb);

    int lm = tid >> 2, lk = (tid & 3) << 2;
    int wk = tid >> 4, wn = tid & 15;
    const float* Xrow = X + (size_t)lm * K;

    float acc[4][2];
    #pragma unroll
    for (int i = 0; i < 4; i++) { acc[i][0] = 0.f; acc[i][1] = 0.f; }

    float4 xr; float wr0, wr1;
    {
        int k0 = kbeg;
        xr = *reinterpret_cast<const float4*>(Xrow + k0 + lk);
        int kg = k0 + wk;
        wr0 = W1[(size_t)kg * N + n0 + wn];
        wr1 = W1[(size_t)kg * N + n0 + wn + 16];
    }
    Xs[0][lk + 0][lm] = xr.x; Xs[0][lk + 1][lm] = xr.y;
    Xs[0][lk + 2][lm] = xr.z; Xs[0][lk + 3][lm] = xr.w;
    Ws[0][wk][wn] = wr0; Ws[0][wk][wn + 16] = wr1;
    __syncthreads();

    for (int it = 0; it < ntiles; it++) {
        int cur = it & 1;
        bool more = (it + 1 < ntiles);
        if (more) {
            int k0 = kbeg + (it + 1) * 16;
            xr = *reinterpret_cast<const float4*>(Xrow + k0 + lk);
            int kg = k0 + wk;
            wr0 = W1[(size_t)kg * N + n0 + wn];
            wr1 = W1[(size_t)kg * N + n0 + wn + 16];
        }
        if (rowact) {
            #pragma unroll
            for (int kk = 0; kk < 16; kk++) {
                float4 xv = *reinterpret_cast<const float4*>(&Xs[cur][kk][m0]);
                float2 wv = *reinterpret_cast<const float2*>(&Ws[cur][kk][nl * 2]);
                acc[0][0] += xv.x * wv.x; acc[0][1] += xv.x * wv.y;
                acc[1][0] += xv.y * wv.x; acc[1][1] += xv.y * wv.y;
                acc[2][0] += xv.z * wv.x; acc[2][1] += xv.z * wv.y;
                acc[3][0] += xv.w * wv.x; acc[3][1] += xv.w * wv.y;
            }
        }
        if (more) {
            int nxt = cur ^ 1;
            Xs[nxt][lk + 0][lm] = xr.x; Xs[nxt][lk + 1][lm] = xr.y;
            Xs[nxt][lk + 2][lm] = xr.z; Xs[nxt][lk + 3][lm] = xr.w;
            Ws[nxt][wk][wn] = wr0; Ws[nxt][wk][wn + 16] = wr1;
        }
        __syncthreads();
    }

    if (!rowact) return;
    int na = n0 + nl * 2;
    #pragma unroll
    for (int j = 0; j < 4; j++) {
        int m = m0 + j;
        if (m < nb) {
            size_t base = ((size_t)(s * BB + m)) * N + na;
            d_part[base] = acc[j][0];
            d_part[base + 1] = acc[j][1];
        }
    }
}

__global__ void k_reduce(int N, int S, const float* __restrict__ b1, int ysel) {
    int idx = blockIdx.x * 256 + threadIdx.x;
    if (idx >= BB * N) return;
    int m = idx / N, n = idx - m * N;
    float v = b1 ? b1[n] : 0.f;
    for (int s = 0; s < S; s++) v += d_part[((size_t)(s * BB + m)) * N + n];
    selbuf(ysel)[(size_t)m * N + n] = v;
}

// ---------------- phase A: split-K2 GEMM h @ [Wd|Wb|Whh] -> d_agp partials ----------------
// grid (144, 2): blockIdx.x -> 32-col tile in concat [att2(512)|gate(2048)|hg(2048)],
// blockIdx.y -> K split (256 each). Raw sums, no bias/activation.
__global__ void __launch_bounds__(256, 2) k_ag(
        const float* __restrict__ Wd, const float* __restrict__ Wb,
        const float* __restrict__ Whh, int t) {
    __shared__ __align__(16) float Xs[2][16][68];
    __shared__ __align__(16) float Ws[2][16][34];

    int n0 = blockIdx.x * 32;       // col in [0, 4608)
    int s = blockIdx.y;
    int nb = d_nb[t];

    const float* W; int wc0, Nw;
    if (n0 < 512)       { W = Wd;  wc0 = n0;        Nw = ATT; }
    else if (n0 < 2560) { W = Wb;  wc0 = n0 - 512;  Nw = 2048; }
    else                { W = Whh; wc0 = n0 - 2560; Nw = 2048; }

    int kbeg = s * 256;
    const int ntiles = 16;

    int tid = threadIdx.x;
    int nl = tid & 15;
    int mg = tid >> 4;
    int m0 = mg << 2;
    bool rowact = (m0 < nb);

    int lm = tid >> 2, lk = (tid & 3) << 2;
    int wk = tid >> 4, wn = tid & 15;
    const float* Xrow = d_h + (size_t)lm * DEC;

    float acc[4][2];
    #pragma unroll
    for (int i = 0; i < 4; i++) { acc[i][0] = 0.f; acc[i][1] = 0.f; }

    float4 xr; float wr0, wr1;
    {
        int k0 = kbeg;
        xr = *reinterpret_cast<const float4*>(Xrow + k0 + lk);
        int kg = k0 + wk;
        wr0 = W[(size_t)kg * Nw + wc0 + wn];
        wr1 = W[(size_t)kg * Nw + wc0 + wn + 16];
    }
    Xs[0][lk + 0][lm] = xr.x; Xs[0][lk + 1][lm] = xr.y;
    Xs[0][lk + 2][lm] = xr.z; Xs[0][lk + 3][lm] = xr.w;
    Ws[0][wk][wn] = wr0; Ws[0][wk][wn + 16] = wr1;
    __syncthreads();

    for (int it = 0; it < ntiles; it++) {
        int cur = it & 1;
        bool more = (it + 1 < ntiles);
        if (more) {
            int k0 = kbeg + (it + 1) * 16;
            xr = *reinterpret_cast<const float4*>(Xrow + k0 + lk);
            int kg = k0 + wk;
            wr0 = W[(size_t)kg * Nw + wc0 + wn];
            wr1 = W[(size_t)kg * Nw + wc0 + wn + 16];
        }
        if (rowact) {
            #pragma unroll
            for (int kk = 0; kk < 16; kk++) {
                float4 xv = *reinterpret_cast<const float4*>(&Xs[cur][kk][m0]);
                float2 wv = *reinterpret_cast<const float2*>(&Ws[cur][kk][nl * 2]);
                acc[0][0] += xv.x * wv.x; acc[0][1] += xv.x * wv.y;
                acc[1][0] += xv.y * wv.x; acc[1][1] += xv.y * wv.y;
                acc[2][0] += xv.z * wv.x; acc[2][1] += xv.z * wv.y;
                acc[3][0] += xv.w * wv.x; acc[3][1] += xv.w * wv.y;
            }
        }
        if (more) {
            int nxt = cur ^ 1;
            Xs[nxt][lk + 0][lm] = xr.x; Xs[nxt][lk + 1][lm] = xr.y;
            Xs[nxt][lk + 2][lm] = xr.z; Xs[nxt][lk + 3][lm] = xr.w;
            Ws[nxt][wk][wn] = wr0; Ws[nxt][wk][wn + 16] = wr1;
        }
        __syncthreads();
    }

    if (!rowact) return;
    int na = n0 + nl * 2;
    #pragma unroll
    for (int j = 0; j < 4; j++) {
        int m = m0 + j;
        if (m < nb) {
            size_t base = ((size_t)(s * BB + m)) * AGC + na;
            d_agp[base] = acc[j][0];
            d_agp[base + 1] = acc[j][1];
        }
    }
}

// ---------------- reduce: g = embc + hg(2) + awe parts(4) + biases, LSTM ----------------
__global__ void k_reduce_lstm(const float* __restrict__ bih, const float* __restrict__ bhh, int t) {
    int idx = blockIdx.x * 256 + threadIdx.x;
    int b = idx >> 9, d = idx & 511;
    if (b >= d_nb[t]) return;
    const float* e   = d_embc + ((size_t)((t << 6) | b)) * 2048;
    const float* hg0 = d_agp + (size_t)b * AGC + 2560;
    const float* hg1 = d_agp + (size_t)(BB + b) * AGC + 2560;
    float gi = bih[d]        + bhh[d]        + e[d]        + hg0[d]        + hg1[d];
    float gf = bih[512 + d]  + bhh[512 + d]  + e[512 + d]  + hg0[512 + d]  + hg1[512 + d];
    float gg = bih[1024 + d] + bhh[1024 + d] + e[1024 + d] + hg0[1024 + d] + hg1[1024 + d];
    float go = bih[1536 + d] + bhh[1536 + d] + e[1536 + d] + hg0[1536 + d] + hg1[1536 + d];
    #pragma unroll
    for (int s = 0; s < 4; s++) {
        const float* p = d_part + ((size_t)(s * BB + b)) * 2048;
        gi += p[d]; gf += p[512 + d]; gg += p[1024 + d]; go += p[1536 + d];
    }
    float c = d_c[b * DEC + d];
    float si = 1.0f / (1.0f + __expf(-gi));
    float sf = 1.0f / (1.0f + __expf(-gf));
    float so = 1.0f / (1.0f + __expf(-go));
    float cn = sf * c + si * tanhf(gg);
    float hn = so * tanhf(cn);
    d_c[b * DEC + d] = cn;
    d_h[b * DEC + d] = hn;
    d_hhist[((size_t)t * BB + b) * DEC + d] = hn;
}

// ---------------- att1 = enc[sorted] @ We + be : tf32 MMA ----------------
__global__ void __launch_bounds__(256, 2) k_att1_mma(const float* __restrict__ enc,
                                                     const float* __restrict__ We,
                                                     const float* __restrict__ be) {
    __shared__ float As[2][16][136];
    __shared__ float Bs[2][16][72];
    int tid = threadIdx.x;
    int warp = tid >> 5, lane = tid & 31;
    int g = lane >> 2, tk = lane & 3;
    int mw = (warp & 3) * 32, nw = (warp >> 2) * 32;
    int rowBase = blockIdx.x * 128, colBase = blockIdx.y * 64;

    int lm = tid >> 1, lk = (tid & 1) << 3;
    int r = rowBase + lm;
    int bidx = r / PP, pidx = r % PP;
    const float* Arow = enc + ((size_t)d_sort_src[bidx] * PP + pidx) * EE;
    int bk = tid >> 4, bn = (tid & 15) << 2;

    float acc[2][4][4];
    #pragma unroll
    for (int i = 0; i < 2; i++)
        #pragma unroll
        for (int j = 0; j < 4; j++)
            #pragma unroll
            for (int q = 0; q < 4; q++) acc[i][j][q] = 0.f;

    float4 av0, av1, bv;
    av0 = *reinterpret_cast<const float4*>(Arow + lk);
    av1 = *reinterpret_cast<const float4*>(Arow + lk + 4);
    bv  = *reinterpret_cast<const float4*>(We + (size_t)bk * ATT + colBase + bn);
    As[0][lk + 0][lm] = tf32r(av0.x); As[0][lk + 1][lm] = tf32r(av0.y);
    As[0][lk + 2][lm] = tf32r(av0.z); As[0][lk + 3][lm] = tf32r(av0.w);
    As[0][lk + 4][lm] = tf32r(av1.x); As[0][lk + 5][lm] = tf32r(av1.y);
    As[0][lk + 6][lm] = tf32r(av1.z); As[0][lk + 7][lm] = tf32r(av1.w);
    *reinterpret_cast<float4*>(&Bs[0][bk][bn]) =
        make_float4(tf32r(bv.x), tf32r(bv.y), tf32r(bv.z), tf32r(bv.w));
    __syncthreads();

    const int ntiles = EE / 16;
    for (int it = 0; it < ntiles; it++) {
        int cur = it & 1;
        bool more = (it + 1 < ntiles);
        if (more) {
            int k0 = (it + 1) * 16;
            av0 = *reinterpret_cast<const float4*>(Arow + k0 + lk);
            av1 = *reinterpret_cast<const float4*>(Arow + k0 + lk + 4);
            bv  = *reinterpret_cast<const float4*>(We + (size_t)(k0 + bk) * ATT + colBase + bn);
        }
        #pragma unroll
        for (int ks = 0; ks < 16; ks += 8) {
            uint32_t a[2][4], bfr[4][2];
            #pragma unroll
            for (int i = 0; i < 2; i++) {
                a[i][0] = __float_as_uint(As[cur][ks + tk][mw + i * 16 + g]);
                a[i][1] = __float_as_uint(As[cur][ks + tk][mw + i * 16 + g + 8]);
                a[i][2] = __float_as_uint(As[cur][ks + tk + 4][mw + i * 16 + g]);
                a[i][3] = __float_as_uint(As[cur][ks + tk + 4][mw + i * 16 + g + 8]);
            }
            #pragma unroll
            for (int j = 0; j < 4; j++) {
                bfr[j][0] = __float_as_uint(Bs[cur][ks + tk][nw + j * 8 + g]);
                bfr[j][1] = __float_as_uint(Bs[cur][ks + tk + 4][nw + j * 8 + g]);
            }
            #pragma unroll
            for (int i = 0; i < 2; i++)
                #pragma unroll
                for (int j = 0; j < 4; j++)
                    mma_tf32(acc[i][j], a[i], bfr[j]);
        }
        if (more) {
            int nxt = cur ^ 1;
            As[nxt][lk + 0][lm] = tf32r(av0.x); As[nxt][lk + 1][lm] = tf32r(av0.y);
            As[nxt][lk + 2][lm] = tf32r(av0.z); As[nxt][lk + 3][lm] = tf32r(av0.w);
            As[nxt][lk + 4][lm] = tf32r(av1.x); As[nxt][lk + 5][lm] = tf32r(av1.y);
            As[nxt][lk + 6][lm] = tf32r(av1.z); As[nxt][lk + 7][lm] = tf32r(av1.w);
            *reinterpret_cast<float4*>(&Bs[nxt][bk][bn]) =
                make_float4(tf32r(bv.x), tf32r(bv.y), tf32r(bv.z), tf32r(bv.w));
        }
        __syncthreads();
    }

    #pragma unroll
    for (int i = 0; i < 2; i++) {
        int row0 = rowBase + mw + i * 16 + g;
        #pragma unroll
        for (int j = 0; j < 4; j++) {
            int col = colBase + nw + j * 8 + tk * 2;
            float be0 = be[col], be1 = be[col + 1];
            float2 o0 = make_float2(acc[i][j][0] + be0, acc[i][j][1] + be1);
            float2 o1 = make_float2(acc[i][j][2] + be0, acc[i][j][3] + be1);
            *reinterpret_cast<float2*>(d_att1 + (size_t)row0 * ATT + col) = o0;
            *reinterpret_cast<float2*>(d_att1 + (size_t)(row0 + 8) * ATT + col) = o1;
        }
    }
}

// ---------------- batched preds: tf32 MMA, compact rows @ Wfc ----------------
__global__ void __launch_bounds__(256, 2) k_preds_mma(const float* __restrict__ Wfc,
                                                      const float* __restrict__ bfc,
                                                      float* __restrict__ out) {
    int total = d_total;
    int rowBase = blockIdx.x * 128;
    if (rowBase >= total) return;
    int colBase = blockIdx.y * 64;

    __shared__ float As[2][16][136];
    __shared__ float Bs[2][16][72];
    int tid = threadIdx.x;
    int warp = tid >> 5, lane = tid & 31;
    int g = lane >> 2, tk = lane & 3;
    int mw = (warp & 3) * 32, nw = (warp >> 2) * 32;

    int lm = tid >> 1, lk = (tid & 1) << 3;
    int r = rowBase + lm;
    bool rvalid = (r < total);
    const float* Arow = d_hhist + (size_t)(rvalid ? d_rowmap[r] : 0) * DEC;
    int bk = tid >> 4, bn = (tid & 15) << 2;
    int bcol = colBase + bn;
    bool cvalid = (bcol < VV);

    float acc[2][4][4];
    #pragma unroll
    for (int i = 0; i < 2; i++)
        #pragma unroll
        for (int j = 0; j < 4; j++)
            #pragma unroll
            for (int q = 0; q < 4; q++) acc[i][j][q] = 0.f;

    float4 av0, av1, bv;
    auto loadA = [&](int k0) {
        if (rvalid) {
            av0 = *reinterpret_cast<const float4*>(Arow + k0 + lk);
            av1 = *reinterpret_cast<const float4*>(Arow + k0 + lk + 4);
        } else {
            av0 = make_float4(0.f, 0.f, 0.f, 0.f);
            av1 = av0;
        }
    };
    auto loadB = [&](int k0) {
        if (cvalid) bv = *reinterpret_cast<const float4*>(Wfc + (size_t)(k0 + bk) * VV + bcol);
        else        bv = make_float4(0.f, 0.f, 0.f, 0.f);
    };

    loadA(0); loadB(0);
    As[0][lk + 0][lm] = tf32r(av0.x); As[0][lk + 1][lm] = tf32r(av0.y);
    As[0][lk + 2][lm] = tf32r(av0.z); As[0][lk + 3][lm] = tf32r(av0.w);
    As[0][lk + 4][lm] = tf32r(av1.x); As[0][lk + 5][lm] = tf32r(av1.y);
    As[0][lk + 6][lm] = tf32r(av1.z); As[0][lk + 7][lm] = tf32r(av1.w);
    *reinterpret_cast<float4*>(&Bs[0][bk][bn]) =
        make_float4(tf32r(bv.x), tf32r(bv.y), tf32r(bv.z), tf32r(bv.w));
    __syncthreads();

    const int ntiles = DEC / 16;
    for (int it = 0; it < ntiles; it++) {
        int cur = it & 1;
        bool more = (it + 1 < ntiles);
        if (more) { loadA((it + 1) * 16); loadB((it + 1) * 16); }
        #pragma unroll
        for (int ks = 0; ks < 16; ks += 8) {
            uint32_t a[2][4], bfr[4][2];
            #pragma unroll
            for (int i = 0; i < 2; i++) {
                a[i][0] = __float_as_uint(As[cur][ks + tk][mw + i * 16 + g]);
                a[i][1] = __float_as_uint(As[cur][ks + tk][mw + i * 16 + g + 8]);
                a[i][2] = __float_as_uint(As[cur][ks + tk + 4][mw + i * 16 + g]);
                a[i][3] = __float_as_uint(As[cur][ks + tk + 4][mw + i * 16 + g + 8]);
            }
            #pragma unroll
            for (int j = 0; j < 4; j++) {
                bfr[j][0] = __float_as_uint(Bs[cur][ks + tk][nw + j * 8 + g]);
                bfr[j][1] = __float_as_uint(Bs[cur][ks + tk + 4][nw + j * 8 + g]);
            }
            #pragma unroll
            for (int i = 0; i < 2; i++)
                #pragma unroll
                for (int j = 0; j < 4; j++)
                    mma_tf32(acc[i][j], a[i], bfr[j]);
        }
        if (more) {
            int nxt = cur ^ 1;
            As[nxt][lk + 0][lm] = tf32r(av0.x); As[nxt][lk + 1][lm] = tf32r(av0.y);
            As[nxt][lk + 2][lm] = tf32r(av0.z); As[nxt][lk + 3][lm] = tf32r(av0.w);
            As[nxt][lk + 4][lm] = tf32r(av1.x); As[nxt][lk + 5][lm] = tf32r(av1.y);
            As[nxt][lk + 6][lm] = tf32r(av1.z); As[nxt][lk + 7][lm] = tf32r(av1.w);
            *reinterpret_cast<float4*>(&Bs[nxt][bk][bn]) =
                make_float4(tf32r(bv.x), tf32r(bv.y), tf32r(bv.z), tf32r(bv.w));
        }
        __syncthreads();
    }

    #pragma unroll
    for (int i = 0; i < 2; i++) {
        #pragma unroll
        for (int j = 0; j < 4; j++) {
            int col = colBase + nw + j * 8 + tk * 2;
            if (col >= VV) continue;
            float bf0 = bfc[col], bf1 = bfc[col + 1];
            #pragma unroll
            for (int h = 0; h < 2; h++) {
                int rr = rowBase + mw + i * 16 + g + h * 8;
                if (rr < total) {
                    int mapped = d_rowmap[rr];
                    int t = mapped >> 6, b = mapped & 63;
                    float* orow = out + ((size_t)b * TT + t) * VV;
                    orow[col]     = acc[i][j][h * 2]     + bf0;
                    orow[col + 1] = acc[i][j][h * 2 + 1] + bf1;
                }
            }
        }
    }
}

// ---------------- embc = embs(active rows) @ Wih[0:512] : tf32 MMA ----------------
__global__ void __launch_bounds__(256, 2) k_embc_mma(const float* __restrict__ emb,
                                                     const int* __restrict__ caps,
                                                     const float* __restrict__ Wih) {
    int total = d_total;
    int rowBase = blockIdx.x * 128;
    if (rowBase >= total) return;
    int colBase = blockIdx.y * 64;
    const int Nw = 2048;

    __shared__ float As[2][16][136];
    __shared__ float Bs[2][16][72];
    int tid = threadIdx.x;
    int warp = tid >> 5, lane = tid & 31;
    int g = lane >> 2, tk = lane & 3;
    int mw = (warp & 3) * 32, nw = (warp >> 2) * 32;

    int lm = tid >> 1, lk = (tid & 1) << 3;
    int r = rowBase + lm;
    bool rvalid = (r < total);
    const float* Arow;
    {
        int mapped = rvalid ? d_rowmap[r] : 0;
        int t = mapped >> 6, b = mapped & 63;
        int cap = caps[d_sort_src[b] * LL + t];
        Arow = emb + (size_t)cap * EMB;
    }
    int bk = tid >> 4, bn = (tid & 15) << 2;
    int bcol = colBase + bn;

    float acc[2][4][4];
    #pragma unroll
    for (int i = 0; i < 2; i++)
        #pragma unroll
        for (int j = 0; j < 4; j++)
            #pragma unroll
            for (int q = 0; q < 4; q++) acc[i][j][q] = 0.f;

    float4 av0, av1, bv;
    auto loadA = [&](int k0) {
        if (rvalid) {
            av0 = *reinterpret_cast<const float4*>(Arow + k0 + lk);
            av1 = *reinterpret_cast<const float4*>(Arow + k0 + lk + 4);
        } else {
            av0 = make_float4(0.f, 0.f, 0.f, 0.f);
            av1 = av0;
        }
    };
    auto loadB = [&](int k0) {
        bv = *reinterpret_cast<const float4*>(Wih + (size_t)(k0 + bk) * Nw + bcol);
    };

    loadA(0); loadB(0);
    As[0][lk + 0][lm] = tf32r(av0.x); As[0][lk + 1][lm] = tf32r(av0.y);
    As[0][lk + 2][lm] = tf32r(av0.z); As[0][lk + 3][lm] = tf32r(av0.w);
    As[0][lk + 4][lm] = tf32r(av1.x); As[0][lk + 5][lm] = tf32r(av1.y);
    As[0][lk + 6][lm] = tf32r(av1.z); As[0][lk + 7][lm] = tf32r(av1.w);
    *reinterpret_cast<float4*>(&Bs[0][bk][bn]) =
        make_float4(tf32r(bv.x), tf32r(bv.y), tf32r(bv.z), tf32r(bv.w));
    __syncthreads();

    const int ntiles = EMB / 16;
    for (int it = 0; it < ntiles; it++) {
        int cur = it & 1;
        bool more = (it + 1 < ntiles);
        if (more) { loadA((it + 1) * 16); loadB((it + 1) * 16); }
        #pragma unroll
        for (int ks = 0; ks < 16; ks += 8) {
            uint32_t a[2][4], bfr[4][2];
            #pragma unroll
            for (int i = 0; i < 2; i++) {
                a[i][0] = __float_as_uint(As[cur][ks + tk][mw + i * 16 + g]);
                a[i][1] = __float_as_uint(As[cur][ks + tk][mw + i * 16 + g + 8]);
                a[i][2] = __float_as_uint(As[cur][ks + tk + 4][mw + i * 16 + g]);
                a[i][3] = __float_as_uint(As[cur][ks + tk + 4][mw + i * 16 + g + 8]);
            }
            #pragma unroll
            for (int j = 0; j < 4; j++) {
                bfr[j][0] = __float_as_uint(Bs[cur][ks + tk][nw + j * 8 + g]);
                bfr[j][1] = __float_as_uint(Bs[cur][ks + tk + 4][nw + j * 8 + g]);
            }
            #pragma unroll
            for (int i = 0; i < 2; i++)
                #pragma unroll
                for (int j = 0; j < 4; j++)
                    mma_tf32(acc[i][j], a[i], bfr[j]);
        }
        if (more) {
            int nxt = cur ^ 1;
            As[nxt][lk + 0][lm] = tf32r(av0.x); As[nxt][lk + 1][lm] = tf32r(av0.y);
            As[nxt][lk + 2][lm] = tf32r(av0.z); As[nxt][lk + 3][lm] = tf32r(av0.w);
            As[nxt][lk + 4][lm] = tf32r(av1.x); As[nxt][lk + 5][lm] = tf32r(av1.y);
            As[nxt][lk + 6][lm] = tf32r(av1.z); As[nxt][lk + 7][lm] = tf32r(av1.w);
            *reinterpret_cast<float4*>(&Bs[nxt][bk][bn]) =
                make_float4(tf32r(bv.x), tf32r(bv.y), tf32r(bv.z), tf32r(bv.w));
        }
        __syncthreads();
    }

    #pragma unroll
    for (int i = 0; i < 2; i++) {
        #pragma unroll
        for (int j = 0; j < 4; j++) {
            int col = colBase + nw + j * 8 + tk * 2;
            #pragma unroll
            for (int h = 0; h < 2; h++) {
                int rr = rowBase + mw + i * 16 + g + h * 8;
                if (rr < total) {
                    int mapped = d_rowmap[rr];
                    float* orow = d_embc + (size_t)mapped * 2048;
                    orow[col]     = acc[i][j][h * 2];
                    orow[col + 1] = acc[i][j][h * 2 + 1];
                }
            }
        }
    }
}

// ---------------- fused: e -> softmax -> awe (reads d_agp partials) ----------------
__global__ void __launch_bounds__(512, 2) k_attend(
        const float* __restrict__ enc,
        const float* __restrict__ Wf, const float* __restrict__ bf,
        const float* __restrict__ bd, const float* __restrict__ bb,
        float* __restrict__ out_alphas, int t) {
    int b = blockIdx.x;
    if (b >= d_nb[t]) return;
    __shared__ __align__(16) float a2[ATT];
    __shared__ __align__(16) float wf[ATT];
    __shared__ float es[PP];
    __shared__ float red[16];
    __shared__ float redsum[16];
    int tid = threadIdx.x;
    const float* p0 = d_agp + (size_t)b * AGC;
    const float* p1 = d_agp + (size_t)(BB + b) * AGC;
    a2[tid] = p0[tid] + p1[tid] + bd[tid];
    wf[tid] = Wf[tid];
    __syncthreads();
    int lane = tid & 31, warp = tid >> 5;

    const float4* a24 = reinterpret_cast<const float4*>(a2);
    const float4* wf4 = reinterpret_cast<const float4*>(wf);
    for (int p = warp; p < PP; p += 16) {
        const float4* row4 = reinterpret_cast<const float4*>(d_att1 + ((size_t)b * PP + p) * ATT);
        float s = 0.f;
        #pragma unroll
        for (int i = 0; i < 4; i++) {
            int idx = lane + i * 32;
            float4 v = row4[idx];
            float4 a = a24[idx];
            float4 w = wf4[idx];
            s += fmaxf(v.x + a.x, 0.f) * w.x;
            s += fmaxf(v.y + a.y, 0.f) * w.y;
            s += fmaxf(v.z + a.z, 0.f) * w.z;
            s += fmaxf(v.w + a.w, 0.f) * w.w;
        }
        #pragma unroll
        for (int off = 16; off > 0; off >>= 1) s += __shfl_xor_sync(0xffffffffu, s, off);
        if (lane == 0) es[p] = s + bf[0];
    }
    __syncthreads();

    float v = (tid < PP) ? es[tid] : -1e30f;
    float m = v;
    #pragma unroll
    for (int off = 16; off > 0; off >>= 1) m = fmaxf(m, __shfl_xor_sync(0xffffffffu, m, off));
    if (lane == 0) red[warp] = m;
    __syncthreads();
    if (tid == 0) {
        float mm = red[0];
        for (int i = 1; i < 16; i++) mm = fmaxf(mm, red[i]);
        red[0] = mm;
    }
    __syncthreads();
    float smax = red[0];
    float ev = (tid < PP) ? __expf(v - smax) : 0.f;
    float s = ev;
    #pragma unroll
    for (int off = 16; off > 0; off >>= 1) s += __shfl_xor_sync(0xffffffffu, s, off);
    if (lane == 0) redsum[warp] = s;
    __syncthreads();
    if (tid == 0) {
        float ss = redsum[0];
        for (int i = 1; i < 16; i++) ss += redsum[i];
        redsum[0] = ss;
    }
    __syncthreads();
    float inv = 1.0f / redsum[0];
    float al = ev * inv;
    if (tid < PP) {
        es[tid] = al;
        out_alphas[((size_t)b * TT + t) * PP + tid] = al;
    }
    __syncthreads();

    int src = d_sort_src[b];
    const float4* enc4 = reinterpret_cast<const float4*>(enc + (size_t)src * PP * EE);
    float4 acc = make_float4(0.f, 0.f, 0.f, 0.f);
    #pragma unroll 4
    for (int p = 0; p < PP; p++) {
        float alp = es[p];
        float4 e4 = enc4[p * 512 + tid];
        acc.x += alp * e4.x; acc.y += alp * e4.y;
        acc.z += alp * e4.z; acc.w += alp * e4.w;
    }
    // gate = sigmoid(p0.gate + p1.gate + bb)
    float4 gp0 = reinterpret_cast<const float4*>(p0 + 512)[tid];
    float4 gp1 = reinterpret_cast<const float4*>(p1 + 512)[tid];
    float4 bbv = reinterpret_cast<const float4*>(bb)[tid];
    float4 gt;
    gt.x = 1.0f / (1.0f + __expf(-(gp0.x + gp1.x + bbv.x)));
    gt.y = 1.0f / (1.0f + __expf(-(gp0.y + gp1.y + bbv.y)));
    gt.z = 1.0f / (1.0f + __expf(-(gp0.z + gp1.z + bbv.z)));
    gt.w = 1.0f / (1.0f + __expf(-(gp0.w + gp1.w + bbv.w)));
    reinterpret_cast<float4*>(d_awe + (size_t)b * EE)[tid] =
        make_float4(acc.x * gt.x, acc.y * gt.y, acc.z * gt.z, acc.w * gt.w);
}

// ---------------- host launch ----------------
extern "C" void kernel_launch(void* const* d_in, const int* in_sizes, int n_in,
                              void* d_out, int out_size) {
    const float* enc  = (const float*)d_in[0];
    const int*   caps = (const int*)d_in[1];
    const int*   clen = (const int*)d_in[2];
    const float* emb  = (const float*)d_in[3];
    const float* We   = (const float*)d_in[4];
    const float* be   = (const float*)d_in[5];
    const float* Wd   = (const float*)d_in[6];
    const float* bd   = (const float*)d_in[7];
    const float* Wf   = (const float*)d_in[8];
    const float* bf   = (const float*)d_in[9];
    const float* Wih  = (const float*)d_in[10];
    const float* bih  = (const float*)d_in[11];
    const float* Whh  = (const float*)d_in[12];
    const float* bhh  = (const float*)d_in[13];
    const float* Wb   = (const float*)d_in[14];
    const float* bb   = (const float*)d_in[15];
    const float* Whi  = (const float*)d_in[16];
    const float* bhi  = (const float*)d_in[17];
    const float* Wci  = (const float*)d_in[18];
    const float* bci  = (const float*)d_in[19];
    const float* Wfc  = (const float*)d_in[20];
    const float* bfc  = (const float*)d_in[21];
    float* out = (float*)d_out;
    float* out_alphas = out + (size_t)BB * TT * VV;

    k_setup<<<1, 64>>>(clen);
    k_zero<<<2048, 256>>>(out, (size_t)out_size);
    k_mean<<<dim3(8, BB), 256>>>(enc);

    // h0 / c0 (split-K 8 over K=2048)
    k_gemm<<<dim3(16, 8), 256>>>(BUF_MEAN, Whi, EE, DEC, -1, 8);
    k_reduce<<<128, 256>>>(DEC, 8, bhi, BUF_H);
    k_gemm<<<dim3(16, 8), 256>>>(BUF_MEAN, Wci, EE, DEC, -1, 8);
    k_reduce<<<128, 256>>>(DEC, 8, bci, BUF_C);

    // att1 via tf32 tensor cores
    k_att1_mma<<<dim3(98, 8), 256>>>(enc, We, be);

    // embc = embs(active rows) @ Wih[0:512] — off the per-step critical path
    k_embc_mma<<<dim3(16, 32), 256>>>(emb, caps, Wih);

    for (int t = 0; t < TT; t++) {
        // phase A: att2/gate/hg partials, split-K 2 (16 tiles/block, 288 blocks)
        k_ag<<<dim3(144, 2), 256>>>(Wd, Wb, Whh, t);
        // attention: sums partials, softmax, gated awe
        k_attend<<<BB, 512>>>(enc, Wf, bf, bd, bb, out_alphas, t);
        // awe part: d_awe @ Wih[512:2560] (K=2048, split-K 4 -> 32 tiles/block)
        k_gemm<<<dim3(64, 4), 256>>>(BUF_AWE, Wih + (size_t)512 * 2048, 2048, 2048, t, 4);
        // g = embc + hg + awe-partials + biases, LSTM pointwise
        k_reduce_lstm<<<128, 256>>>(bih, bhh, t);
    }

    // batched vocab projection via tf32 tensor cores
    k_preds_mma<<<dim3(16, 157), 256>>>(Wfc, bfc, out);
}

// round 10
// speedup vs baseline: 1.3548x; 1.0752x over previous
#include <cuda_runtime.h>
#include <cuda_bf16.h>
#include <cstdint>

// Problem constants
#define BB 64
#define PP 196
#define EE 2048
#define LL 32
#define VV 10000
#define EMB 512
#define DEC 512
#define ATT 512
#define TT 31   // L-1 steps

// ---------------- device scratch ----------------
__device__ __align__(16) int   d_sort_src[BB];
__device__ __align__(16) int   d_nb[TT + 1];
__device__ int   d_total;
__device__ __align__(16) int   d_rowmap[BB * TT];
__device__ __align__(16) float d_mean[BB * EE];
__device__ __align__(16) float d_h[BB * DEC];
__device__ __align__(16) float d_c[BB * DEC];
__device__ __align__(16) float d_hhist[(size_t)TT * BB * DEC];
__device__ __align__(16) float d_att1[(size_t)BB * PP * ATT];
__device__ __align__(16) float d_awe[BB * EE];
__device__ __align__(16) float d_embc[(size_t)TT * BB * 2048];
__device__ __align__(16) float d_part[8 * BB * 2048];
// phase-A partials: [split(2)][b(64)][col(4608)] — 0..511 att2, 512..2559 gate, 2560..4607 hg
#define AGC 4608
__device__ __align__(16) float d_agp[2 * BB * AGC];

#define BUF_MEAN 0
#define BUF_H    1
#define BUF_C    2
#define BUF_AWE  5

__device__ __forceinline__ float* selbuf(int s) {
    switch (s) {
        case BUF_MEAN: return d_mean;
        case BUF_H:    return d_h;
        case BUF_C:    return d_c;
        case BUF_AWE:  return d_awe;
        default:       return nullptr;
    }
}

// ---------------- tf32 helpers ----------------
__device__ __forceinline__ float tf32r(float f) {
    uint32_t u;
    asm("cvt.rna.tf32.f32 %0, %1;" : "=r"(u) : "f"(f));
    return __uint_as_float(u);
}
__device__ __forceinline__ void mma_tf32(float* c, const uint32_t* a, const uint32_t* b) {
    asm volatile("mma.sync.aligned.m16n8k8.row.col.f32.tf32.tf32.f32 "
        "{%0,%1,%2,%3}, {%4,%5,%6,%7}, {%8,%9}, {%0,%1,%2,%3};"
        : "+f"(c[0]), "+f"(c[1]), "+f"(c[2]), "+f"(c[3])
        : "r"(a[0]), "r"(a[1]), "r"(a[2]), "r"(a[3]), "r"(b[0]), "r"(b[1]));
}

// ---------------- setup ----------------
__global__ void k_setup(const int* __restrict__ cap_len) {
    __shared__ int lens[BB];
    __shared__ int nbs[TT + 1];
    __shared__ int off[TT + 1];
    int b = threadIdx.x;
    if (b < BB) lens[b] = cap_len[b];
    __syncthreads();
    if (b < BB) {
        int rank = 0;
        int lb = lens[b];
        for (int j = 0; j < BB; j++) {
            int lj = lens[j];
            if (lj > lb || (lj == lb && j < b)) rank++;
        }
        d_sort_src[rank] = b;
    }
    if (b <= TT) {
        int cnt = 0;
        for (int j = 0; j < BB; j++) if (lens[j] - 1 > b) cnt++;
        d_nb[b] = cnt;
        nbs[b] = cnt;
    }
    __syncthreads();
    if (b == 0) {
        int a = 0;
        for (int t = 0; t < TT; t++) { off[t] = a; a += nbs[t]; }
        d_total = a;
    }
    __syncthreads();
    if (b < BB) {
        for (int t = 0; t < TT; t++)
            if (b < nbs[t]) d_rowmap[off[t] + b] = (t << 6) | b;
    }
}

__global__ void k_zero(float* __restrict__ out, size_t n) {
    size_t i = (size_t)blockIdx.x * blockDim.x + threadIdx.x;
    size_t stride = (size_t)gridDim.x * blockDim.x;
    for (; i < n; i += stride) out[i] = 0.0f;
}

__global__ void k_mean(const float* __restrict__ enc) {
    int b = blockIdx.y;
    int e = blockIdx.x * 256 + threadIdx.x;
    const float* base = enc + (size_t)d_sort_src[b] * PP * EE + e;
    float s = 0.0f;
    #pragma unroll 7
    for (int p = 0; p < PP; p++) s += base[(size_t)p * EE];
    d_mean[b * EE + e] = s * (1.0f / 196.0f);
}

// ---------------- split-K GEMM, KTILE=32, into d_part ----------------
// Y-cols n0 pick WA (n0 < colSplit, width NA) or WB (width NB).
__global__ void __launch_bounds__(256, 2) k_gemm32(
        int xsel, const float* __restrict__ WA, const float* __restrict__ WB,
        int colSplit, int NA, int NB, int Nout, int K, int S, int t) {
    __shared__ __align__(16) float Xs[2][32][68];
    __shared__ __align__(16) float Ws[2][32][34];

    const float* X = selbuf(xsel);
    int tid = threadIdx.x;
    int nb = (t >= 0) ? d_nb[t] : BB;
    int n0 = blockIdx.x * 32;

    const float* W; int wc0, NW;
    if (n0 < colSplit) { W = WA; wc0 = n0; NW = NA; }
    else               { W = WB; wc0 = n0 - colSplit; NW = NB; }

    int s = blockIdx.y;
    int kbeg = s * (K / S);
    int ntiles = (K / S) / 32;

    int nl = tid & 15;
    int mg = tid >> 4;
    int m0 = mg << 2;
    bool rowact = (m0 < nb);

    int lm = tid >> 2, lk = (tid & 3) << 2;
    int wk = tid >> 4, wn = tid & 15;
    const float* Xrow = X + (size_t)lm * K;

    float acc[4][2];
    #pragma unroll
    for (int i = 0; i < 4; i++) { acc[i][0] = 0.f; acc[i][1] = 0.f; }

    float4 xr0, xr1; float wr00, wr01, wr10, wr11;
    auto loadG = [&](int k0) {
        xr0 = *reinterpret_cast<const float4*>(Xrow + k0 + lk);
        xr1 = *reinterpret_cast<const float4*>(Xrow + k0 + lk + 16);
        int kg = k0 + wk;
        wr00 = W[(size_t)kg * NW + wc0 + wn];
        wr01 = W[(size_t)kg * NW + wc0 + wn + 16];
        wr10 = W[(size_t)(kg + 16) * NW + wc0 + wn];
        wr11 = W[(size_t)(kg + 16) * NW + wc0 + wn + 16];
    };
    auto stS = [&](int buf) {
        Xs[buf][lk + 0][lm] = xr0.x; Xs[buf][lk + 1][lm] = xr0.y;
        Xs[buf][lk + 2][lm] = xr0.z; Xs[buf][lk + 3][lm] = xr0.w;
        Xs[buf][lk + 16][lm] = xr1.x; Xs[buf][lk + 17][lm] = xr1.y;
        Xs[buf][lk + 18][lm] = xr1.z; Xs[buf][lk + 19][lm] = xr1.w;
        Ws[buf][wk][wn] = wr00; Ws[buf][wk][wn + 16] = wr01;
        Ws[buf][wk + 16][wn] = wr10; Ws[buf][wk + 16][wn + 16] = wr11;
    };

    loadG(kbeg);
    stS(0);
    __syncthreads();

    for (int it = 0; it < ntiles; it++) {
        int cur = it & 1;
        bool more = (it + 1 < ntiles);
        if (more) loadG(kbeg + (it + 1) * 32);
        if (rowact) {
            #pragma unroll
            for (int kk = 0; kk < 32; kk++) {
                float4 xv = *reinterpret_cast<const float4*>(&Xs[cur][kk][m0]);
                float2 wv = *reinterpret_cast<const float2*>(&Ws[cur][kk][nl * 2]);
                acc[0][0] += xv.x * wv.x; acc[0][1] += xv.x * wv.y;
                acc[1][0] += xv.y * wv.x; acc[1][1] += xv.y * wv.y;
                acc[2][0] += xv.z * wv.x; acc[2][1] += xv.z * wv.y;
                acc[3][0] += xv.w * wv.x; acc[3][1] += xv.w * wv.y;
            }
        }
        if (more) stS(cur ^ 1);
        __syncthreads();
    }

    if (!rowact) return;
    int na = n0 + nl * 2;
    #pragma unroll
    for (int j = 0; j < 4; j++) {
        int m = m0 + j;
        if (m < nb) {
            size_t base = ((size_t)(s * BB + m)) * Nout + na;
            d_part[base] = acc[j][0];
            d_part[base + 1] = acc[j][1];
        }
    }
}

// reduce combined h0/c0 (N=1024, S=8)
__global__ void k_reduce_hc(const float* __restrict__ bhi, const float* __restrict__ bci) {
    int idx = blockIdx.x * 256 + threadIdx.x;
    if (idx >= BB * 1024) return;
    int m = idx >> 10, n = idx & 1023;
    float v = 0.f;
    #pragma unroll
    for (int s = 0; s < 8; s++) v += d_part[((size_t)(s * BB + m)) * 1024 + n];
    if (n < 512) d_h[m * 512 + n] = v + bhi[n];
    else         d_c[m * 512 + (n - 512)] = v + bci[n - 512];
}

// ---------------- phase A: split-K2 KTILE=32 GEMM h @ [Wd|Wb|Whh] -> d_agp ----------------
__global__ void __launch_bounds__(256, 2) k_ag(
        const float* __restrict__ Wd, const float* __restrict__ Wb,
        const float* __restrict__ Whh, int t) {
    __shared__ __align__(16) float Xs[2][32][68];
    __shared__ __align__(16) float Ws[2][32][34];

    int n0 = blockIdx.x * 32;       // col in [0, 4608)
    int s = blockIdx.y;
    int nb = d_nb[t];

    const float* W; int wc0, NW;
    if (n0 < 512)       { W = Wd;  wc0 = n0;        NW = ATT; }
    else if (n0 < 2560) { W = Wb;  wc0 = n0 - 512;  NW = 2048; }
    else                { W = Whh; wc0 = n0 - 2560; NW = 2048; }

    int kbeg = s * 256;
    const int ntiles = 8;

    int tid = threadIdx.x;
    int nl = tid & 15;
    int mg = tid >> 4;
    int m0 = mg << 2;
    bool rowact = (m0 < nb);

    int lm = tid >> 2, lk = (tid & 3) << 2;
    int wk = tid >> 4, wn = tid & 15;
    const float* Xrow = d_h + (size_t)lm * DEC;

    float acc[4][2];
    #pragma unroll
    for (int i = 0; i < 4; i++) { acc[i][0] = 0.f; acc[i][1] = 0.f; }

    float4 xr0, xr1; float wr00, wr01, wr10, wr11;
    auto loadG = [&](int k0) {
        xr0 = *reinterpret_cast<const float4*>(Xrow + k0 + lk);
        xr1 = *reinterpret_cast<const float4*>(Xrow + k0 + lk + 16);
        int kg = k0 + wk;
        wr00 = W[(size_t)kg * NW + wc0 + wn];
        wr01 = W[(size_t)kg * NW + wc0 + wn + 16];
        wr10 = W[(size_t)(kg + 16) * NW + wc0 + wn];
        wr11 = W[(size_t)(kg + 16) * NW + wc0 + wn + 16];
    };
    auto stS = [&](int buf) {
        Xs[buf][lk + 0][lm] = xr0.x; Xs[buf][lk + 1][lm] = xr0.y;
        Xs[buf][lk + 2][lm] = xr0.z; Xs[buf][lk + 3][lm] = xr0.w;
        Xs[buf][lk + 16][lm] = xr1.x; Xs[buf][lk + 17][lm] = xr1.y;
        Xs[buf][lk + 18][lm] = xr1.z; Xs[buf][lk + 19][lm] = xr1.w;
        Ws[buf][wk][wn] = wr00; Ws[buf][wk][wn + 16] = wr01;
        Ws[buf][wk + 16][wn] = wr10; Ws[buf][wk + 16][wn + 16] = wr11;
    };

    loadG(kbeg);
    stS(0);
    __syncthreads();

    for (int it = 0; it < ntiles; it++) {
        int cur = it & 1;
        bool more = (it + 1 < ntiles);
        if (more) loadG(kbeg + (it + 1) * 32);
        if (rowact) {
            #pragma unroll
            for (int kk = 0; kk < 32; kk++) {
                float4 xv = *reinterpret_cast<const float4*>(&Xs[cur][kk][m0]);
                float2 wv = *reinterpret_cast<const float2*>(&Ws[cur][kk][nl * 2]);
                acc[0][0] += xv.x * wv.x; acc[0][1] += xv.x * wv.y;
                acc[1][0] += xv.y * wv.x; acc[1][1] += xv.y * wv.y;
                acc[2][0] += xv.z * wv.x; acc[2][1] += xv.z * wv.y;
                acc[3][0] += xv.w * wv.x; acc[3][1] += xv.w * wv.y;
            }
        }
        if (more) stS(cur ^ 1);
        __syncthreads();
    }

    if (!rowact) return;
    int na = n0 + nl * 2;
    #pragma unroll
    for (int j = 0; j < 4; j++) {
        int m = m0 + j;
        if (m < nb) {
            size_t base = ((size_t)(s * BB + m)) * AGC + na;
            d_agp[base] = acc[j][0];
            d_agp[base + 1] = acc[j][1];
        }
    }
}

// ---------------- reduce: g = embc + hg(2) + awe parts(4) + biases, LSTM ----------------
__global__ void k_reduce_lstm(const float* __restrict__ bih, const float* __restrict__ bhh, int t) {
    int idx = blockIdx.x * 256 + threadIdx.x;
    int b = idx >> 9, d = idx & 511;
    if (b >= d_nb[t]) return;
    const float* e   = d_embc + ((size_t)((t << 6) | b)) * 2048;
    const float* hg0 = d_agp + (size_t)b * AGC + 2560;
    const float* hg1 = d_agp + (size_t)(BB + b) * AGC + 2560;
    float gi = bih[d]        + bhh[d]        + e[d]        + hg0[d]        + hg1[d];
    float gf = bih[512 + d]  + bhh[512 + d]  + e[512 + d]  + hg0[512 + d]  + hg1[512 + d];
    float gg = bih[1024 + d] + bhh[1024 + d] + e[1024 + d] + hg0[1024 + d] + hg1[1024 + d];
    float go = bih[1536 + d] + bhh[1536 + d] + e[1536 + d] + hg0[1536 + d] + hg1[1536 + d];
    #pragma unroll
    for (int s = 0; s < 4; s++) {
        const float* p = d_part + ((size_t)(s * BB + b)) * 2048;
        gi += p[d]; gf += p[512 + d]; gg += p[1024 + d]; go += p[1536 + d];
    }
    float c = d_c[b * DEC + d];
    float si = 1.0f / (1.0f + __expf(-gi));
    float sf = 1.0f / (1.0f + __expf(-gf));
    float so = 1.0f / (1.0f + __expf(-go));
    float cn = sf * c + si * tanhf(gg);
    float hn = so * tanhf(cn);
    d_c[b * DEC + d] = cn;
    d_h[b * DEC + d] = hn;
    d_hhist[((size_t)t * BB + b) * DEC + d] = hn;
}

// ---------------- att1 = enc[sorted] @ We + be : tf32 MMA ----------------
__global__ void __launch_bounds__(256, 2) k_att1_mma(const float* __restrict__ enc,
                                                     const float* __restrict__ We,
                                                     const float* __restrict__ be) {
    __shared__ float As[2][16][136];
    __shared__ float Bs[2][16][72];
    int tid = threadIdx.x;
    int warp = tid >> 5, lane = tid & 31;
    int g = lane >> 2, tk = lane & 3;
    int mw = (warp & 3) * 32, nw = (warp >> 2) * 32;
    int rowBase = blockIdx.x * 128, colBase = blockIdx.y * 64;

    int lm = tid >> 1, lk = (tid & 1) << 3;
    int r = rowBase + lm;
    int bidx = r / PP, pidx = r % PP;
    const float* Arow = enc + ((size_t)d_sort_src[bidx] * PP + pidx) * EE;
    int bk = tid >> 4, bn = (tid & 15) << 2;

    float acc[2][4][4];
    #pragma unroll
    for (int i = 0; i < 2; i++)
        #pragma unroll
        for (int j = 0; j < 4; j++)
            #pragma unroll
            for (int q = 0; q < 4; q++) acc[i][j][q] = 0.f;

    float4 av0, av1, bv;
    av0 = *reinterpret_cast<const float4*>(Arow + lk);
    av1 = *reinterpret_cast<const float4*>(Arow + lk + 4);
    bv  = *reinterpret_cast<const float4*>(We + (size_t)bk * ATT + colBase + bn);
    As[0][lk + 0][lm] = tf32r(av0.x); As[0][lk + 1][lm] = tf32r(av0.y);
    As[0][lk + 2][lm] = tf32r(av0.z); As[0][lk + 3][lm] = tf32r(av0.w);
    As[0][lk + 4][lm] = tf32r(av1.x); As[0][lk + 5][lm] = tf32r(av1.y);
    As[0][lk + 6][lm] = tf32r(av1.z); As[0][lk + 7][lm] = tf32r(av1.w);
    *reinterpret_cast<float4*>(&Bs[0][bk][bn]) =
        make_float4(tf32r(bv.x), tf32r(bv.y), tf32r(bv.z), tf32r(bv.w));
    __syncthreads();

    const int ntiles = EE / 16;
    for (int it = 0; it < ntiles; it++) {
        int cur = it & 1;
        bool more = (it + 1 < ntiles);
        if (more) {
            int k0 = (it + 1) * 16;
            av0 = *reinterpret_cast<const float4*>(Arow + k0 + lk);
            av1 = *reinterpret_cast<const float4*>(Arow + k0 + lk + 4);
            bv  = *reinterpret_cast<const float4*>(We + (size_t)(k0 + bk) * ATT + colBase + bn);
        }
        #pragma unroll
        for (int ks = 0; ks < 16; ks += 8) {
            uint32_t a[2][4], bfr[4][2];
            #pragma unroll
            for (int i = 0; i < 2; i++) {
                a[i][0] = __float_as_uint(As[cur][ks + tk][mw + i * 16 + g]);
                a[i][1] = __float_as_uint(As[cur][ks + tk][mw + i * 16 + g + 8]);
                a[i][2] = __float_as_uint(As[cur][ks + tk + 4][mw + i * 16 + g]);
                a[i][3] = __float_as_uint(As[cur][ks + tk + 4][mw + i * 16 + g + 8]);
            }
            #pragma unroll
            for (int j = 0; j < 4; j++) {
                bfr[j][0] = __float_as_uint(Bs[cur][ks + tk][nw + j * 8 + g]);
                bfr[j][1] = __float_as_uint(Bs[cur][ks + tk + 4][nw + j * 8 + g]);
            }
            #pragma unroll
            for (int i = 0; i < 2; i++)
                #pragma unroll
                for (int j = 0; j < 4; j++)
                    mma_tf32(acc[i][j], a[i], bfr[j]);
        }
        if (more) {
            int nxt = cur ^ 1;
            As[nxt][lk + 0][lm] = tf32r(av0.x); As[nxt][lk + 1][lm] = tf32r(av0.y);
            As[nxt][lk + 2][lm] = tf32r(av0.z); As[nxt][lk + 3][lm] = tf32r(av0.w);
            As[nxt][lk + 4][lm] = tf32r(av1.x); As[nxt][lk + 5][lm] = tf32r(av1.y);
            As[nxt][lk + 6][lm] = tf32r(av1.z); As[nxt][lk + 7][lm] = tf32r(av1.w);
            *reinterpret_cast<float4*>(&Bs[nxt][bk][bn]) =
                make_float4(tf32r(bv.x), tf32r(bv.y), tf32r(bv.z), tf32r(bv.w));
        }
        __syncthreads();
    }

    #pragma unroll
    for (int i = 0; i < 2; i++) {
        int row0 = rowBase + mw + i * 16 + g;
        #pragma unroll
        for (int j = 0; j < 4; j++) {
            int col = colBase + nw + j * 8 + tk * 2;
            float be0 = be[col], be1 = be[col + 1];
            float2 o0 = make_float2(acc[i][j][0] + be0, acc[i][j][1] + be1);
            float2 o1 = make_float2(acc[i][j][2] + be0, acc[i][j][3] + be1);
            *reinterpret_cast<float2*>(d_att1 + (size_t)row0 * ATT + col) = o0;
            *reinterpret_cast<float2*>(d_att1 + (size_t)(row0 + 8) * ATT + col) = o1;
        }
    }
}

// ---------------- batched preds: tf32 MMA, compact rows @ Wfc ----------------
__global__ void __launch_bounds__(256, 2) k_preds_mma(const float* __restrict__ Wfc,
                                                      const float* __restrict__ bfc,
                                                      float* __restrict__ out) {
    int total = d_total;
    int rowBase = blockIdx.x * 128;
    if (rowBase >= total) return;
    int colBase = blockIdx.y * 64;

    __shared__ float As[2][16][136];
    __shared__ float Bs[2][16][72];
    int tid = threadIdx.x;
    int warp = tid >> 5, lane = tid & 31;
    int g = lane >> 2, tk = lane & 3;
    int mw = (warp & 3) * 32, nw = (warp >> 2) * 32;

    int lm = tid >> 1, lk = (tid & 1) << 3;
    int r = rowBase + lm;
    bool rvalid = (r < total);
    const float* Arow = d_hhist + (size_t)(rvalid ? d_rowmap[r] : 0) * DEC;
    int bk = tid >> 4, bn = (tid & 15) << 2;
    int bcol = colBase + bn;
    bool cvalid = (bcol < VV);

    float acc[2][4][4];
    #pragma unroll
    for (int i = 0; i < 2; i++)
        #pragma unroll
        for (int j = 0; j < 4; j++)
            #pragma unroll
            for (int q = 0; q < 4; q++) acc[i][j][q] = 0.f;

    float4 av0, av1, bv;
    auto loadA = [&](int k0) {
        if (rvalid) {
            av0 = *reinterpret_cast<const float4*>(Arow + k0 + lk);
            av1 = *reinterpret_cast<const float4*>(Arow + k0 + lk + 4);
        } else {
            av0 = make_float4(0.f, 0.f, 0.f, 0.f);
            av1 = av0;
        }
    };
    auto loadB = [&](int k0) {
        if (cvalid) bv = *reinterpret_cast<const float4*>(Wfc + (size_t)(k0 + bk) * VV + bcol);
        else        bv = make_float4(0.f, 0.f, 0.f, 0.f);
    };

    loadA(0); loadB(0);
    As[0][lk + 0][lm] = tf32r(av0.x); As[0][lk + 1][lm] = tf32r(av0.y);
    As[0][lk + 2][lm] = tf32r(av0.z); As[0][lk + 3][lm] = tf32r(av0.w);
    As[0][lk + 4][lm] = tf32r(av1.x); As[0][lk + 5][lm] = tf32r(av1.y);
    As[0][lk + 6][lm] = tf32r(av1.z); As[0][lk + 7][lm] = tf32r(av1.w);
    *reinterpret_cast<float4*>(&Bs[0][bk][bn]) =
        make_float4(tf32r(bv.x), tf32r(bv.y), tf32r(bv.z), tf32r(bv.w));
    __syncthreads();

    const int ntiles = DEC / 16;
    for (int it = 0; it < ntiles; it++) {
        int cur = it & 1;
        bool more = (it + 1 < ntiles);
        if (more) { loadA((it + 1) * 16); loadB((it + 1) * 16); }
        #pragma unroll
        for (int ks = 0; ks < 16; ks += 8) {
            uint32_t a[2][4], bfr[4][2];
            #pragma unroll
            for (int i = 0; i < 2; i++) {
                a[i][0] = __float_as_uint(As[cur][ks + tk][mw + i * 16 + g]);
                a[i][1] = __float_as_uint(As[cur][ks + tk][mw + i * 16 + g + 8]);
                a[i][2] = __float_as_uint(As[cur][ks + tk + 4][mw + i * 16 + g]);
                a[i][3] = __float_as_uint(As[cur][ks + tk + 4][mw + i * 16 + g + 8]);
            }
            #pragma unroll
            for (int j = 0; j < 4; j++) {
                bfr[j][0] = __float_as_uint(Bs[cur][ks + tk][nw + j * 8 + g]);
                bfr[j][1] = __float_as_uint(Bs[cur][ks + tk + 4][nw + j * 8 + g]);
            }
            #pragma unroll
            for (int i = 0; i < 2; i++)
                #pragma unroll
                for (int j = 0; j < 4; j++)
                    mma_tf32(acc[i][j], a[i], bfr[j]);
        }
        if (more) {
            int nxt = cur ^ 1;
            As[nxt][lk + 0][lm] = tf32r(av0.x); As[nxt][lk + 1][lm] = tf32r(av0.y);
            As[nxt][lk + 2][lm] = tf32r(av0.z); As[nxt][lk + 3][lm] = tf32r(av0.w);
            As[nxt][lk + 4][lm] = tf32r(av1.x); As[nxt][lk + 5][lm] = tf32r(av1.y);
            As[nxt][lk + 6][lm] = tf32r(av1.z); As[nxt][lk + 7][lm] = tf32r(av1.w);
            *reinterpret_cast<float4*>(&Bs[nxt][bk][bn]) =
                make_float4(tf32r(bv.x), tf32r(bv.y), tf32r(bv.z), tf32r(bv.w));
        }
        __syncthreads();
    }

    #pragma unroll
    for (int i = 0; i < 2; i++) {
        #pragma unroll
        for (int j = 0; j < 4; j++) {
            int col = colBase + nw + j * 8 + tk * 2;
            if (col >= VV) continue;
            float bf0 = bfc[col], bf1 = bfc[col + 1];
            #pragma unroll
            for (int h = 0; h < 2; h++) {
                int rr = rowBase + mw + i * 16 + g + h * 8;
                if (rr < total) {
                    int mapped = d_rowmap[rr];
                    int t = mapped >> 6, b = mapped & 63;
                    float* orow = out + ((size_t)b * TT + t) * VV;
                    orow[col]     = acc[i][j][h * 2]     + bf0;
                    orow[col + 1] = acc[i][j][h * 2 + 1] + bf1;
                }
            }
        }
    }
}

// ---------------- embc = embs(active rows) @ Wih[0:512] : tf32 MMA ----------------
__global__ void __launch_bounds__(256, 2) k_embc_mma(const float* __restrict__ emb,
                                                     const int* __restrict__ caps,
                                                     const float* __restrict__ Wih) {
    int total = d_total;
    int rowBase = blockIdx.x * 128;
    if (rowBase >= total) return;
    int colBase = blockIdx.y * 64;
    const int Nw = 2048;

    __shared__ float As[2][16][136];
    __shared__ float Bs[2][16][72];
    int tid = threadIdx.x;
    int warp = tid >> 5, lane = tid & 31;
    int g = lane >> 2, tk = lane & 3;
    int mw = (warp & 3) * 32, nw = (warp >> 2) * 32;

    int lm = tid >> 1, lk = (tid & 1) << 3;
    int r = rowBase + lm;
    bool rvalid = (r < total);
    const float* Arow;
    {
        int mapped = rvalid ? d_rowmap[r] : 0;
        int t = mapped >> 6, b = mapped & 63;
        int cap = caps[d_sort_src[b] * LL + t];
        Arow = emb + (size_t)cap * EMB;
    }
    int bk = tid >> 4, bn = (tid & 15) << 2;
    int bcol = colBase + bn;

    float acc[2][4][4];
    #pragma unroll
    for (int i = 0; i < 2; i++)
        #pragma unroll
        for (int j = 0; j < 4; j++)
            #pragma unroll
            for (int q = 0; q < 4; q++) acc[i][j][q] = 0.f;

    float4 av0, av1, bv;
    auto loadA = [&](int k0) {
        if (rvalid) {
            av0 = *reinterpret_cast<const float4*>(Arow + k0 + lk);
            av1 = *reinterpret_cast<const float4*>(Arow + k0 + lk + 4);
        } else {
            av0 = make_float4(0.f, 0.f, 0.f, 0.f);
            av1 = av0;
        }
    };
    auto loadB = [&](int k0) {
        bv = *reinterpret_cast<const float4*>(Wih + (size_t)(k0 + bk) * Nw + bcol);
    };

    loadA(0); loadB(0);
    As[0][lk + 0][lm] = tf32r(av0.x); As[0][lk + 1][lm] = tf32r(av0.y);
    As[0][lk + 2][lm] = tf32r(av0.z); As[0][lk + 3][lm] = tf32r(av0.w);
    As[0][lk + 4][lm] = tf32r(av1.x); As[0][lk + 5][lm] = tf32r(av1.y);
    As[0][lk + 6][lm] = tf32r(av1.z); As[0][lk + 7][lm] = tf32r(av1.w);
    *reinterpret_cast<float4*>(&Bs[0][bk][bn]) =
        make_float4(tf32r(bv.x), tf32r(bv.y), tf32r(bv.z), tf32r(bv.w));
    __syncthreads();

    const int ntiles = EMB / 16;
    for (int it = 0; it < ntiles; it++) {
        int cur = it & 1;
        bool more = (it + 1 < ntiles);
        if (more) { loadA((it + 1) * 16); loadB((it + 1) * 16); }
        #pragma unroll
        for (int ks = 0; ks < 16; ks += 8) {
            uint32_t a[2][4], bfr[4][2];
            #pragma unroll
            for (int i = 0; i < 2; i++) {
                a[i][0] = __float_as_uint(As[cur][ks + tk][mw + i * 16 + g]);
                a[i][1] = __float_as_uint(As[cur][ks + tk][mw + i * 16 + g + 8]);
                a[i][2] = __float_as_uint(As[cur][ks + tk + 4][mw + i * 16 + g]);
                a[i][3] = __float_as_uint(As[cur][ks + tk + 4][mw + i * 16 + g + 8]);
            }
            #pragma unroll
            for (int j = 0; j < 4; j++) {
                bfr[j][0] = __float_as_uint(Bs[cur][ks + tk][nw + j * 8 + g]);
                bfr[j][1] = __float_as_uint(Bs[cur][ks + tk + 4][nw + j * 8 + g]);
            }
            #pragma unroll
            for (int i = 0; i < 2; i++)
                #pragma unroll
                for (int j = 0; j < 4; j++)
                    mma_tf32(acc[i][j], a[i], bfr[j]);
        }
        if (more) {
            int nxt = cur ^ 1;
            As[nxt][lk + 0][lm] = tf32r(av0.x); As[nxt][lk + 1][lm] = tf32r(av0.y);
            As[nxt][lk + 2][lm] = tf32r(av0.z); As[nxt][lk + 3][lm] = tf32r(av0.w);
            As[nxt][lk + 4][lm] = tf32r(av1.x); As[nxt][lk + 5][lm] = tf32r(av1.y);
            As[nxt][lk + 6][lm] = tf32r(av1.z); As[nxt][lk + 7][lm] = tf32r(av1.w);
            *reinterpret_cast<float4*>(&Bs[nxt][bk][bn]) =
                make_float4(tf32r(bv.x), tf32r(bv.y), tf32r(bv.z), tf32r(bv.w));
        }
        __syncthreads();
    }

    #pragma unroll
    for (int i = 0; i < 2; i++) {
        #pragma unroll
        for (int j = 0; j < 4; j++) {
            int col = colBase + nw + j * 8 + tk * 2;
            #pragma unroll
            for (int h = 0; h < 2; h++) {
                int rr = rowBase + mw + i * 16 + g + h * 8;
                if (rr < total) {
                    int mapped = d_rowmap[rr];
                    float* orow = d_embc + (size_t)mapped * 2048;
                    orow[col]     = acc[i][j][h * 2];
                    orow[col + 1] = acc[i][j][h * 2 + 1];
                }
            }
        }
    }
}

// ---------------- fused: e -> softmax -> awe, 1024 threads, p-loop split in half ----------------
__global__ void __launch_bounds__(1024, 1) k_attend(
        const float* __restrict__ enc,
        const float* __restrict__ Wf, const float* __restrict__ bf,
        const float* __restrict__ bd, const float* __restrict__ bb,
        float* __restrict__ out_alphas, int t) {
    int b = blockIdx.x;
    if (b >= d_nb[t]) return;
    __shared__ __align__(16) float a2[ATT];
    __shared__ __align__(16) float wf[ATT];
    __shared__ float es[PP + 4];
    __shared__ float red[32];
    __shared__ float redsum[32];
    __shared__ __align__(16) float awe_sh[2048];
    int tid = threadIdx.x;
    const float* p0 = d_agp + (size_t)b * AGC;
    const float* p1 = d_agp + (size_t)(BB + b) * AGC;
    if (tid < 512) {
        a2[tid] = p0[tid] + p1[tid] + bd[tid];
        wf[tid] = Wf[tid];
    }
    __syncthreads();
    int lane = tid & 31, warp = tid >> 5;

    const float4* a24 = reinterpret_cast<const float4*>(a2);
    const float4* wf4 = reinterpret_cast<const float4*>(wf);
    for (int p = warp; p < PP; p += 32) {
        const float4* row4 = reinterpret_cast<const float4*>(d_att1 + ((size_t)b * PP + p) * ATT);
        float s = 0.f;
        #pragma unroll
        for (int i = 0; i < 4; i++) {
            int idx = lane + i * 32;
            float4 v = row4[idx];
            float4 a = a24[idx];
            float4 w = wf4[idx];
            s += fmaxf(v.x + a.x, 0.f) * w.x;
            s += fmaxf(v.y + a.y, 0.f) * w.y;
            s += fmaxf(v.z + a.z, 0.f) * w.z;
            s += fmaxf(v.w + a.w, 0.f) * w.w;
        }
        #pragma unroll
        for (int off = 16; off > 0; off >>= 1) s += __shfl_xor_sync(0xffffffffu, s, off);
        if (lane == 0) es[p] = s + bf[0];
    }
    __syncthreads();

    float v = (tid < PP) ? es[tid] : -1e30f;
    float m = v;
    #pragma unroll
    for (int off = 16; off > 0; off >>= 1) m = fmaxf(m, __shfl_xor_sync(0xffffffffu, m, off));
    if (lane == 0) red[warp] = m;
    __syncthreads();
    if (tid == 0) {
        float mm = red[0];
        for (int i = 1; i < 32; i++) mm = fmaxf(mm, red[i]);
        red[0] = mm;
    }
    __syncthreads();
    float smax = red[0];
    float ev = (tid < PP) ? __expf(v - smax) : 0.f;
    float s = ev;
    #pragma unroll
    for (int off = 16; off > 0; off >>= 1) s += __shfl_xor_sync(0xffffffffu, s, off);
    if (lane == 0) redsum[warp] = s;
    __syncthreads();
    if (tid == 0) {
        float ss = redsum[0];
        for (int i = 1; i < 32; i++) ss += redsum[i];
        redsum[0] = ss;
    }
    __syncthreads();
    float inv = 1.0f / redsum[0];
    float al = ev * inv;
    if (tid < PP) {
        es[tid] = al;
        out_alphas[((size_t)b * TT + t) * PP + tid] = al;
    }
    __syncthreads();

    // awe: 2 halves of the p-range; each thread covers float4 column c4
    int src = d_sort_src[b];
    int half = tid >> 9;      // 0 or 1
    int c4 = tid & 511;       // float4 column 0..511 (covers 2048 floats)
    const float4* enc4 = reinterpret_cast<const float4*>(enc + (size_t)src * PP * EE);
    int pbeg = half * 98, pend = pbeg + 98;
    float4 acc = make_float4(0.f, 0.f, 0.f, 0.f);
    #pragma unroll 2
    for (int p = pbeg; p < pend; p++) {
        float alp = es[p];
        float4 e4 = enc4[p * 512 + c4];
        acc.x += alp * e4.x; acc.y += alp * e4.y;
        acc.z += alp * e4.z; acc.w += alp * e4.w;
    }
    float4* awe4 = reinterpret_cast<float4*>(awe_sh);
    if (half == 1) awe4[c4] = acc;
    __syncthreads();
    if (half == 0) {
        float4 o = awe4[c4];
        acc.x += o.x; acc.y += o.y; acc.z += o.z; acc.w += o.w;
        // gate = sigmoid(p0.gate + p1.gate + bb)
        float4 gp0 = reinterpret_cast<const float4*>(p0 + 512)[c4];
        float4 gp1 = reinterpret_cast<const float4*>(p1 + 512)[c4];
        float4 bbv = reinterpret_cast<const float4*>(bb)[c4];
        float4 gt;
        gt.x = 1.0f / (1.0f + __expf(-(gp0.x + gp1.x + bbv.x)));
        gt.y = 1.0f / (1.0f + __expf(-(gp0.y + gp1.y + bbv.y)));
        gt.z = 1.0f / (1.0f + __expf(-(gp0.z + gp1.z + bbv.z)));
        gt.w = 1.0f / (1.0f + __expf(-(gp0.w + gp1.w + bbv.w)));
        reinterpret_cast<float4*>(d_awe + (size_t)b * EE)[c4] =
            make_float4(acc.x * gt.x, acc.y * gt.y, acc.z * gt.z, acc.w * gt.w);
    }
}

// ---------------- host launch ----------------
extern "C" void kernel_launch(void* const* d_in, const int* in_sizes, int n_in,
                              void* d_out, int out_size) {
    const float* enc  = (const float*)d_in[0];
    const int*   caps = (const int*)d_in[1];
    const int*   clen = (const int*)d_in[2];
    const float* emb  = (const float*)d_in[3];
    const float* We   = (const float*)d_in[4];
    const float* be   = (const float*)d_in[5];
    const float* Wd   = (const float*)d_in[6];
    const float* bd   = (const float*)d_in[7];
    const float* Wf   = (const float*)d_in[8];
    const float* bf   = (const float*)d_in[9];
    const float* Wih  = (const float*)d_in[10];
    const float* bih  = (const float*)d_in[11];
    const float* Whh  = (const float*)d_in[12];
    const float* bhh  = (const float*)d_in[13];
    const float* Wb   = (const float*)d_in[14];
    const float* bb   = (const float*)d_in[15];
    const float* Whi  = (const float*)d_in[16];
    const float* bhi  = (const float*)d_in[17];
    const float* Wci  = (const float*)d_in[18];
    const float* bci  = (const float*)d_in[19];
    const float* Wfc  = (const float*)d_in[20];
    const float* bfc  = (const float*)d_in[21];
    float* out = (float*)d_out;
    float* out_alphas = out + (size_t)BB * TT * VV;

    k_setup<<<1, 64>>>(clen);
    k_zero<<<2048, 256>>>(out, (size_t)out_size);
    k_mean<<<dim3(8, BB), 256>>>(enc);

    // h0 + c0 in ONE split-K GEMM (concat [Whi|Wci], N=1024, K=2048, S=8)
    k_gemm32<<<dim3(32, 8), 256>>>(BUF_MEAN, Whi, Wci, 512, 512, 512, 1024, EE, 8, -1);
    k_reduce_hc<<<256, 256>>>(bhi, bci);

    // att1 via tf32 tensor cores
    k_att1_mma<<<dim3(98, 8), 256>>>(enc, We, be);

    // embc = embs(active rows) @ Wih[0:512]
    k_embc_mma<<<dim3(16, 32), 256>>>(emb, caps, Wih);

    for (int t = 0; t < TT; t++) {
        // phase A: att2/gate/hg partials, split-K 2, KTILE 32 (8 tiles/block)
        k_ag<<<dim3(144, 2), 256>>>(Wd, Wb, Whh, t);
        // attention: sums partials, softmax, gated awe (1024 thr, halved p-loop)
        k_attend<<<BB, 1024>>>(enc, Wf, bf, bd, bb, out_alphas, t);
        // awe part: d_awe @ Wih[512:2560] (K=2048, S=4, KTILE 32 -> 16 tiles)
        k_gemm32<<<dim3(64, 4), 256>>>(BUF_AWE, Wih + (size_t)512 * 2048, nullptr,
                                       1 << 30, 2048, 0, 2048, 2048, 4, t);
        // g = embc + hg + awe-partials + biases, LSTM pointwise
        k_reduce_lstm<<<128, 256>>>(bih, bhh, t);
    }

    // batched vocab projection via tf32 tensor cores
    k_preds_mma<<<dim3(16, 157), 256>>>(Wfc, bfc, out);
}